// round 5
// baseline (speedup 1.0000x reference)
#include <cuda_runtime.h>
#include <cstdint>

#define D 128
#define NMAX 100000

// ---- scratch (static device globals; no allocation allowed) ----
__device__ float  g_h[(size_t)NMAX * D];     // h = x@W + b
__device__ float  g_acc[(size_t)NMAX * D];   // scatter-add accumulator
__device__ float  g_feat[(size_t)NMAX * D];  // BN output / next layer input
__device__ float  g_dinv[NMAX];              // deg^-0.5
__device__ double g_stats[2 * D];            // per-feature sum, sumsq
__device__ float  g_coeff[2 * D];            // BN fused mul, add

// ------------------------------------------------------------------
// Degree: count edges per source node (row), then dinv = rsqrt(cnt+1)
// ------------------------------------------------------------------
__global__ void k_count(const int* __restrict__ ei, int E) {
    for (int i = blockIdx.x * blockDim.x + threadIdx.x; i < E;
         i += gridDim.x * blockDim.x)
        atomicAdd(&g_dinv[ei[i]], 1.0f);
}

__global__ void k_dinv(int M) {
    int i = blockIdx.x * blockDim.x + threadIdx.x;
    if (i < M) g_dinv[i] = rsqrtf(g_dinv[i] + 1.0f);
}

// ------------------------------------------------------------------
// SGEMM: C[M,128] = A[M,128] @ W[128,128] + bias
// 128x128 block tile, BK=16, 256 threads, 8x8 micro-tile per thread
// ------------------------------------------------------------------
__global__ __launch_bounds__(256, 2)
void k_gemm(const float* __restrict__ A, const float* __restrict__ W,
            const float* __restrict__ bias, float* __restrict__ C, int M)
{
    __shared__ float As[16][128];   // [k][row]
    __shared__ float Ws[16][128];   // [k][col]
    const int tid  = threadIdx.x;
    const int m0   = blockIdx.x * 128;
    const int trow = (tid >> 4) << 3;   // 0..120 step 8
    const int tcol = (tid & 15) << 3;   // 0..120 step 8

    float acc[8][8];
    #pragma unroll
    for (int i = 0; i < 8; i++)
        #pragma unroll
        for (int j = 0; j < 8; j++) acc[i][j] = 0.0f;

    for (int k0 = 0; k0 < 128; k0 += 16) {
        // load A tile (128 rows x 16 cols): 512 float4, 2 per thread
        #pragma unroll
        for (int it = 0; it < 2; it++) {
            int q  = tid + it * 256;
            int r  = q >> 2;
            int qc = (q & 3) << 2;         // 0,4,8,12
            int row = m0 + r;
            float4 v = make_float4(0.f, 0.f, 0.f, 0.f);
            if (row < M)
                v = *(const float4*)(A + (size_t)row * 128 + k0 + qc);
            As[qc + 0][r] = v.x; As[qc + 1][r] = v.y;
            As[qc + 2][r] = v.z; As[qc + 3][r] = v.w;
        }
        // load W tile (16 rows x 128 cols)
        #pragma unroll
        for (int it = 0; it < 2; it++) {
            int q = tid + it * 256;
            int k = q >> 5;
            int c = (q & 31) << 2;
            *(float4*)(&Ws[k][c]) =
                *(const float4*)(W + (size_t)(k0 + k) * 128 + c);
        }
        __syncthreads();
        #pragma unroll
        for (int kk = 0; kk < 16; kk++) {
            float a[8], w[8];
            *(float4*)(a)     = *(const float4*)(&As[kk][trow]);
            *(float4*)(a + 4) = *(const float4*)(&As[kk][trow + 4]);
            *(float4*)(w)     = *(const float4*)(&Ws[kk][tcol]);
            *(float4*)(w + 4) = *(const float4*)(&Ws[kk][tcol + 4]);
            #pragma unroll
            for (int i = 0; i < 8; i++)
                #pragma unroll
                for (int j = 0; j < 8; j++)
                    acc[i][j] += a[i] * w[j];
        }
        __syncthreads();
    }

    float bj[8];
    *(float4*)(bj)     = *(const float4*)(bias + tcol);
    *(float4*)(bj + 4) = *(const float4*)(bias + tcol + 4);
    #pragma unroll
    for (int i = 0; i < 8; i++) {
        int row = m0 + trow + i;
        if (row < M) {
            float4 o0 = make_float4(acc[i][0] + bj[0], acc[i][1] + bj[1],
                                    acc[i][2] + bj[2], acc[i][3] + bj[3]);
            float4 o1 = make_float4(acc[i][4] + bj[4], acc[i][5] + bj[5],
                                    acc[i][6] + bj[6], acc[i][7] + bj[7]);
            *(float4*)(C + (size_t)row * 128 + tcol)     = o0;
            *(float4*)(C + (size_t)row * 128 + tcol + 4) = o1;
        }
    }
}

// ------------------------------------------------------------------
// Edge aggregation: one warp per edge (lane owns 4 features),
// 4 edges per iteration for MLP. Vector red.global.add.v4.f32.
// acc[col] += relu(h[row] + ea@We + be) * dinv[row]*dinv[col]
// ------------------------------------------------------------------
__global__ __launch_bounds__(256)
void k_edge(const float* __restrict__ h, const int* __restrict__ ei,
            const float* __restrict__ ea, const float* __restrict__ We,
            const float* __restrict__ be, int E)
{
    const int lane = threadIdx.x & 31;
    const int warp = (blockIdx.x * blockDim.x + threadIdx.x) >> 5;
    const int nw   = (gridDim.x * blockDim.x) >> 5;
    const int f    = lane << 2;

    const float4 w0 = *(const float4*)(We + f);
    const float4 w1 = *(const float4*)(We + D + f);
    const float4 w2 = *(const float4*)(We + 2 * D + f);
    const float4 b4 = *(const float4*)(be + f);

    for (int e0 = warp * 4; e0 < E; e0 += nw * 4) {
        bool   val[4];
        int    cc[4];
        float  a0[4], a1[4], a2[4], nrm[4];
        float4 hv[4];
        #pragma unroll
        for (int u = 0; u < 4; u++) {
            int e  = e0 + u;
            val[u] = (e < E);
            int es = val[u] ? e : e0;
            int r  = ei[es];
            cc[u]  = ei[E + es];
            a0[u]  = ea[3 * es + 0];
            a1[u]  = ea[3 * es + 1];
            a2[u]  = ea[3 * es + 2];
            nrm[u] = g_dinv[r] * g_dinv[cc[u]];
            hv[u]  = *(const float4*)(h + (size_t)r * D + f);
        }
        #pragma unroll
        for (int u = 0; u < 4; u++) {
            float4 v;
            v.x = fmaxf(hv[u].x + b4.x + a0[u]*w0.x + a1[u]*w1.x + a2[u]*w2.x, 0.f) * nrm[u];
            v.y = fmaxf(hv[u].y + b4.y + a0[u]*w0.y + a1[u]*w1.y + a2[u]*w2.y, 0.f) * nrm[u];
            v.z = fmaxf(hv[u].z + b4.z + a0[u]*w0.z + a1[u]*w1.z + a2[u]*w2.z, 0.f) * nrm[u];
            v.w = fmaxf(hv[u].w + b4.w + a0[u]*w0.w + a1[u]*w1.w + a2[u]*w2.w, 0.f) * nrm[u];
            if (val[u]) {
                float* p = g_acc + (size_t)cc[u] * D + f;
                asm volatile("red.global.add.v4.f32 [%0], {%1,%2,%3,%4};"
                             :: "l"(p), "f"(v.x), "f"(v.y), "f"(v.z), "f"(v.w)
                             : "memory");
            }
        }
    }
}

// ------------------------------------------------------------------
// BN stats over relu(acc): per-feature sum & sumsq (double accum)
// ------------------------------------------------------------------
__global__ void k_bnstats(int M) {
    const int f = threadIdx.x;   // 128 threads = 128 features
    double s = 0.0, s2 = 0.0;
    for (int r = blockIdx.x; r < M; r += gridDim.x) {
        float v = fmaxf(g_acc[(size_t)r * D + f], 0.0f);
        s  += (double)v;
        s2 += (double)v * (double)v;
    }
    atomicAdd(&g_stats[f], s);
    atomicAdd(&g_stats[D + f], s2);
}

__global__ void k_bncoeff(const float* __restrict__ g,
                          const float* __restrict__ bt, int M) {
    const int f = threadIdx.x;
    double mean = g_stats[f] / (double)M;
    double var  = g_stats[D + f] / (double)M - mean * mean;
    float mul = g[f] * rsqrtf((float)var + 1e-5f);
    g_coeff[f]     = mul;
    g_coeff[D + f] = bt[f] - (float)mean * mul;
}

// feat = relu(acc) * mul + add   (fused relu + batchnorm affine)
__global__ void k_bnapply(int M) {
    const int nq = M * (D / 4);
    const float4* av = (const float4*)g_acc;
    float4*       ov = (float4*)g_feat;
    const float4* cf = (const float4*)g_coeff;
    for (int i = blockIdx.x * blockDim.x + threadIdx.x; i < nq;
         i += gridDim.x * blockDim.x) {
        int fq = i & 31;
        float4 v   = av[i];
        float4 mul = cf[fq];
        float4 ad  = cf[32 + fq];
        float4 o;
        o.x = fmaxf(v.x, 0.f) * mul.x + ad.x;
        o.y = fmaxf(v.y, 0.f) * mul.y + ad.y;
        o.z = fmaxf(v.z, 0.f) * mul.z + ad.z;
        o.w = fmaxf(v.w, 0.f) * mul.w + ad.w;
        ov[i] = o;
    }
}

// ------------------------------------------------------------------
extern "C" void kernel_launch(void* const* d_in, const int* in_sizes, int n_in,
                              void* d_out, int out_size)
{
    const float* x  = (const float*)d_in[0];
    const int*   ei = (const int*)d_in[1];
    const float* ea = (const float*)d_in[2];
    // per-layer params: W,b,We,be,g,bt at [3..8],[9..14],[15..20]
    const float* Wp[3]  = {(const float*)d_in[3],  (const float*)d_in[9],  (const float*)d_in[15]};
    const float* bp[3]  = {(const float*)d_in[4],  (const float*)d_in[10], (const float*)d_in[16]};
    const float* Wep[3] = {(const float*)d_in[5],  (const float*)d_in[11], (const float*)d_in[17]};
    const float* bep[3] = {(const float*)d_in[6],  (const float*)d_in[12], (const float*)d_in[18]};
    const float* gp[3]  = {(const float*)d_in[7],  (const float*)d_in[13], (const float*)d_in[19]};
    const float* btp[3] = {(const float*)d_in[8],  (const float*)d_in[14], (const float*)d_in[20]};
    const float* Wl = (const float*)d_in[21];
    const float* bl = (const float*)d_in[22];

    const int M = in_sizes[0] / D;   // nodes
    const int E = in_sizes[1] / 2;   // edges

    // IMPORTANT: always resolve __device__ symbols via the runtime.
    // On GB300, the raw host-shadow symbol is ATS-dereferenceable from the
    // GPU (reads host .bss zeros) — a silent wrong-answer, not a trap.
    void *p_h, *p_acc, *p_feat, *p_dinv, *p_stats;
    cudaGetSymbolAddress(&p_h, g_h);
    cudaGetSymbolAddress(&p_acc, g_acc);
    cudaGetSymbolAddress(&p_feat, g_feat);
    cudaGetSymbolAddress(&p_dinv, g_dinv);
    cudaGetSymbolAddress(&p_stats, g_stats);

    // degrees (same for all layers)
    cudaMemsetAsync(p_dinv, 0, (size_t)M * sizeof(float));
    k_count<<<2048, 256>>>(ei, E);
    k_dinv<<<(M + 255) / 256, 256>>>(M);

    const int gemm_grid = (M + 127) / 128;
    const float* in = x;
    for (int L = 0; L < 3; L++) {
        k_gemm<<<gemm_grid, 256>>>(in, Wp[L], bp[L], (float*)p_h, M);
        cudaMemsetAsync(p_acc, 0, (size_t)M * D * sizeof(float));
        k_edge<<<1536, 256>>>((const float*)p_h, ei, ea, Wep[L], bep[L], E);
        cudaMemsetAsync(p_stats, 0, 2 * D * sizeof(double));
        k_bnstats<<<1024, 128>>>(M);
        k_bncoeff<<<1, 128>>>(gp[L], btp[L], M);
        k_bnapply<<<2048, 256>>>(M);
        in = (const float*)p_feat;
    }
    k_gemm<<<gemm_grid, 256>>>((const float*)p_feat, Wl, bl, (float*)d_out, M);
}

// round 8
// speedup vs baseline: 1.1742x; 1.1742x over previous
#include <cuda_runtime.h>
#include <cuda_bf16.h>
#include <cstdint>

#define D 128
#define NMAX 100000
#define WTILE (128 * 128)
#define PITCH 272                       // smem row pitch in bytes (136 bf16)
#define ATILE (128 * PITCH)             // 34816 B per 128x128 bf16 tile
#define DYNSMEM (4 * ATILE)             // Ah, Al, Bh, Bl = 139264 B

// ---- scratch (static device globals; no allocation allowed) ----
__device__ float  g_h[(size_t)NMAX * D];     // GEMM out / edge gather src
__device__ float  g_acc[(size_t)NMAX * D];   // scatter-add accumulator
__device__ float  g_dinv[NMAX];              // deg^-0.5
__device__ double g_stats[2 * D];            // per-feature sum, sumsq
__device__ float  g_coeff[2 * D];            // BN fused mul, add
__device__ __align__(16) __nv_bfloat16 g_wbh[4 * WTILE];  // W^T hi (bf16)
__device__ __align__(16) __nv_bfloat16 g_wbl[4 * WTILE];  // W^T lo residual

__device__ __forceinline__ uint32_t pack_bf2(__nv_bfloat16 lo, __nv_bfloat16 hi) {
    return ((uint32_t)__bfloat16_as_ushort(hi) << 16) |
           (uint32_t)__bfloat16_as_ushort(lo);
}

// ------------------------------------------------------------------
// Degree: count edges per source node (row), then dinv = rsqrt(cnt+1)
// ------------------------------------------------------------------
__global__ void k_count(const int* __restrict__ ei, int E) {
    for (int i = blockIdx.x * blockDim.x + threadIdx.x; i < E;
         i += gridDim.x * blockDim.x)
        atomicAdd(&g_dinv[ei[i]], 1.0f);
}

__global__ void k_dinv(int M) {
    int i = blockIdx.x * blockDim.x + threadIdx.x;
    if (i < M) g_dinv[i] = rsqrtf(g_dinv[i] + 1.0f);
}

// ------------------------------------------------------------------
// Weight conversion: Wt[n][k] = split_bf16(W[k][n]) for 4 matrices
// ------------------------------------------------------------------
__global__ void k_wconv(const float* __restrict__ W0, const float* __restrict__ W1,
                        const float* __restrict__ W2, const float* __restrict__ W3) {
    int i = blockIdx.x * blockDim.x + threadIdx.x;   // 0 .. 4*16384-1
    if (i >= 4 * WTILE) return;
    int m = i >> 14, r = i & (WTILE - 1);
    int n = r >> 7, k = r & 127;
    const float* W = (m == 0) ? W0 : (m == 1) ? W1 : (m == 2) ? W2 : W3;
    float v = W[k * 128 + n];
    __nv_bfloat16 h = __float2bfloat16_rn(v);
    g_wbh[i] = h;
    g_wbl[i] = __float2bfloat16_rn(v - __bfloat162float(h));
}

// ------------------------------------------------------------------
// Tensor-core split-bf16 GEMM via mma.sync.m16n8k16 (portable HMMA):
//   C[M,128] = act(A)[M,128] @ W[128,128] + bias
//   act(A) = coeff ? relu(A)*mul+add : A   (fused BN, kills k_bnapply)
//   C = Ah@Bh + Ah@Bl + Al@Bh  (fp32 accumulators)
// 256 threads / 8 warps, 128-row tile, K=N=128 resident in smem.
// 272B row pitch makes all fragment LDS conflict-free (bank == lane).
// ------------------------------------------------------------------
__global__ __launch_bounds__(256, 1)
void k_gemm_mma(const float* __restrict__ A,
                const __nv_bfloat16* __restrict__ Bh,
                const __nv_bfloat16* __restrict__ Bl,
                const float* __restrict__ bias,
                const float* __restrict__ coeff,   // nullable [mul|add]
                float* __restrict__ C, int M)
{
    extern __shared__ char dsm[];
    char* pAh = dsm;
    char* pAl = dsm + ATILE;
    char* pBh = dsm + 2 * ATILE;
    char* pBl = dsm + 3 * ATILE;
    __shared__ float s_bias[128], s_mul[128], s_add[128];

    const int tid  = threadIdx.x;
    const int warp = tid >> 5;
    const int lane = tid & 31;
    const int g    = lane >> 2;        // fragment group row
    const int tig  = lane & 3;         // thread-in-group
    const int m0   = blockIdx.x * 128;
    const bool useBN = (coeff != nullptr);

    if (tid < 128) {
        s_bias[tid] = bias[tid];
        if (useBN) { s_mul[tid] = coeff[tid]; s_add[tid] = coeff[128 + tid]; }
    }
    // BUGFIX (R7): s_mul/s_add are read below by ALL threads — must
    // barrier after the tid<128 writes or BN coeffs are garbage.
    __syncthreads();

    // ---- load weight tiles (bf16 [n][k], k contiguous) into smem ----
    #pragma unroll
    for (int it = 0; it < 8; it++) {
        int q = it * 256 + tid;
        int row = q >> 4, c8 = (q & 15) << 3;   // 8 bf16 = 16B
        *(uint4*)(pBh + row * PITCH + c8 * 2) = *(const uint4*)(Bh + row * 128 + c8);
        *(uint4*)(pBl + row * PITCH + c8 * 2) = *(const uint4*)(Bl + row * 128 + c8);
    }

    // ---- load A block, fused relu+BN, split to bf16 hi/lo ----
    #pragma unroll
    for (int it = 0; it < 16; it++) {
        int q = it * 256 + tid;
        int row = q >> 5, c4 = (q & 31) << 2;   // 4 floats
        int grow = m0 + row;
        float4 v = make_float4(0.f, 0.f, 0.f, 0.f);
        if (grow < M) v = *(const float4*)(A + (size_t)grow * 128 + c4);
        float vv[4] = {v.x, v.y, v.z, v.w};
        if (useBN) {
            #pragma unroll
            for (int j = 0; j < 4; j++)
                vv[j] = fmaxf(vv[j], 0.f) * s_mul[c4 + j] + s_add[c4 + j];
        }
        __nv_bfloat16 h[4], l[4];
        #pragma unroll
        for (int j = 0; j < 4; j++) {
            h[j] = __float2bfloat16_rn(vv[j]);
            l[j] = __float2bfloat16_rn(vv[j] - __bfloat162float(h[j]));
        }
        uint2 hw, lw;
        hw.x = pack_bf2(h[0], h[1]); hw.y = pack_bf2(h[2], h[3]);
        lw.x = pack_bf2(l[0], l[1]); lw.y = pack_bf2(l[2], l[3]);
        *(uint2*)(pAh + row * PITCH + c4 * 2) = hw;
        *(uint2*)(pAl + row * PITCH + c4 * 2) = lw;
    }
    __syncthreads();

    // ---- MMA mainloop: warp owns rows [warp*16, warp*16+16) x N=128 ----
    float acc[16][4];
    #pragma unroll
    for (int nt = 0; nt < 16; nt++)
        #pragma unroll
        for (int j = 0; j < 4; j++) acc[nt][j] = 0.0f;

    const int arow = warp * 16;
    #pragma unroll
    for (int p = 0; p < 3; p++) {
        const char* As = (p == 2) ? pAl : pAh;
        const char* Bs = (p == 1) ? pBl : pBh;
        // A fragments for all 8 k-steps
        uint32_t a[8][4];
        #pragma unroll
        for (int k8 = 0; k8 < 8; k8++) {
            uint32_t base = (uint32_t)(arow + g) * PITCH + (uint32_t)k8 * 32 + 4u * tig;
            a[k8][0] = *(const uint32_t*)(As + base);
            a[k8][1] = *(const uint32_t*)(As + base + 8 * PITCH);
            a[k8][2] = *(const uint32_t*)(As + base + 16);
            a[k8][3] = *(const uint32_t*)(As + base + 8 * PITCH + 16);
        }
        #pragma unroll
        for (int nt = 0; nt < 16; nt++) {
            uint32_t brow = (uint32_t)(nt * 8 + g) * PITCH + 4u * tig;
            #pragma unroll
            for (int k8 = 0; k8 < 8; k8++) {
                uint32_t b0 = *(const uint32_t*)(Bs + brow + k8 * 32);
                uint32_t b1 = *(const uint32_t*)(Bs + brow + k8 * 32 + 16);
                asm volatile(
                    "mma.sync.aligned.m16n8k16.row.col.f32.bf16.bf16.f32 "
                    "{%0,%1,%2,%3}, {%4,%5,%6,%7}, {%8,%9}, {%0,%1,%2,%3};"
                    : "+f"(acc[nt][0]), "+f"(acc[nt][1]),
                      "+f"(acc[nt][2]), "+f"(acc[nt][3])
                    : "r"(a[k8][0]), "r"(a[k8][1]), "r"(a[k8][2]), "r"(a[k8][3]),
                      "r"(b0), "r"(b1));
            }
        }
    }

    // ---- epilogue: + bias, store fp32 ----
    const int r0 = m0 + arow + g;
    const int r1 = r0 + 8;
    #pragma unroll
    for (int nt = 0; nt < 16; nt++) {
        int col = nt * 8 + tig * 2;
        float bx = s_bias[col], by = s_bias[col + 1];
        if (r0 < M) {
            float2 o = make_float2(acc[nt][0] + bx, acc[nt][1] + by);
            *(float2*)(C + (size_t)r0 * 128 + col) = o;
        }
        if (r1 < M) {
            float2 o = make_float2(acc[nt][2] + bx, acc[nt][3] + by);
            *(float2*)(C + (size_t)r1 * 128 + col) = o;
        }
    }
}

// ------------------------------------------------------------------
// Edge aggregation: one warp per edge (lane owns 4 features),
// 4 edges per iteration. Vector red.global.add.v4.f32.
// acc[col] += relu(h[row] + ea@We + be) * dinv[row]*dinv[col]
// ------------------------------------------------------------------
__global__ __launch_bounds__(256)
void k_edge(const float* __restrict__ h, const int* __restrict__ ei,
            const float* __restrict__ ea, const float* __restrict__ We,
            const float* __restrict__ be, int E)
{
    const int lane = threadIdx.x & 31;
    const int warp = (blockIdx.x * blockDim.x + threadIdx.x) >> 5;
    const int nw   = (gridDim.x * blockDim.x) >> 5;
    const int f    = lane << 2;

    const float4 w0 = *(const float4*)(We + f);
    const float4 w1 = *(const float4*)(We + D + f);
    const float4 w2 = *(const float4*)(We + 2 * D + f);
    const float4 b4 = *(const float4*)(be + f);

    for (int e0 = warp * 4; e0 < E; e0 += nw * 4) {
        bool   val[4];
        int    cc[4];
        float  a0[4], a1[4], a2[4], nrm[4];
        float4 hv[4];
        #pragma unroll
        for (int u = 0; u < 4; u++) {
            int e  = e0 + u;
            val[u] = (e < E);
            int es = val[u] ? e : e0;
            int r  = ei[es];
            cc[u]  = ei[E + es];
            a0[u]  = ea[3 * es + 0];
            a1[u]  = ea[3 * es + 1];
            a2[u]  = ea[3 * es + 2];
            nrm[u] = g_dinv[r] * g_dinv[cc[u]];
            hv[u]  = *(const float4*)(h + (size_t)r * D + f);
        }
        #pragma unroll
        for (int u = 0; u < 4; u++) {
            float4 v;
            v.x = fmaxf(hv[u].x + b4.x + a0[u]*w0.x + a1[u]*w1.x + a2[u]*w2.x, 0.f) * nrm[u];
            v.y = fmaxf(hv[u].y + b4.y + a0[u]*w0.y + a1[u]*w1.y + a2[u]*w2.y, 0.f) * nrm[u];
            v.z = fmaxf(hv[u].z + b4.z + a0[u]*w0.z + a1[u]*w1.z + a2[u]*w2.z, 0.f) * nrm[u];
            v.w = fmaxf(hv[u].w + b4.w + a0[u]*w0.w + a1[u]*w1.w + a2[u]*w2.w, 0.f) * nrm[u];
            if (val[u]) {
                float* p = g_acc + (size_t)cc[u] * D + f;
                asm volatile("red.global.add.v4.f32 [%0], {%1,%2,%3,%4};"
                             :: "l"(p), "f"(v.x), "f"(v.y), "f"(v.z), "f"(v.w)
                             : "memory");
            }
        }
    }
}

// ------------------------------------------------------------------
// BN stats over relu(acc): per-feature sum & sumsq (double accum)
// ------------------------------------------------------------------
__global__ void k_bnstats(int M) {
    const int f = threadIdx.x;   // 128 threads = 128 features
    double s = 0.0, s2 = 0.0;
    for (int r = blockIdx.x; r < M; r += gridDim.x) {
        float v = fmaxf(g_acc[(size_t)r * D + f], 0.0f);
        s  += (double)v;
        s2 += (double)v * (double)v;
    }
    atomicAdd(&g_stats[f], s);
    atomicAdd(&g_stats[D + f], s2);
}

__global__ void k_bncoeff(const float* __restrict__ g,
                          const float* __restrict__ bt, int M) {
    const int f = threadIdx.x;
    double mean = g_stats[f] / (double)M;
    double var  = g_stats[D + f] / (double)M - mean * mean;
    float mul = g[f] * rsqrtf((float)var + 1e-5f);
    g_coeff[f]     = mul;
    g_coeff[D + f] = bt[f] - (float)mean * mul;
}

// ------------------------------------------------------------------
extern "C" void kernel_launch(void* const* d_in, const int* in_sizes, int n_in,
                              void* d_out, int out_size)
{
    const float* x  = (const float*)d_in[0];
    const int*   ei = (const int*)d_in[1];
    const float* ea = (const float*)d_in[2];
    const float* Wp[3]  = {(const float*)d_in[3],  (const float*)d_in[9],  (const float*)d_in[15]};
    const float* bp[3]  = {(const float*)d_in[4],  (const float*)d_in[10], (const float*)d_in[16]};
    const float* Wep[3] = {(const float*)d_in[5],  (const float*)d_in[11], (const float*)d_in[17]};
    const float* bep[3] = {(const float*)d_in[6],  (const float*)d_in[12], (const float*)d_in[18]};
    const float* gp[3]  = {(const float*)d_in[7],  (const float*)d_in[13], (const float*)d_in[19]};
    const float* btp[3] = {(const float*)d_in[8],  (const float*)d_in[14], (const float*)d_in[20]};
    const float* Wl = (const float*)d_in[21];
    const float* bl = (const float*)d_in[22];

    const int M = in_sizes[0] / D;   // nodes
    const int E = in_sizes[1] / 2;   // edges

    // Resolve __device__ symbols via the runtime (GB300 ATS makes the raw
    // host-shadow symbol silently dereferenceable from the GPU!)
    void *p_h, *p_acc, *p_dinv, *p_stats, *p_coeff, *p_wbh, *p_wbl;
    cudaGetSymbolAddress(&p_h, g_h);
    cudaGetSymbolAddress(&p_acc, g_acc);
    cudaGetSymbolAddress(&p_dinv, g_dinv);
    cudaGetSymbolAddress(&p_stats, g_stats);
    cudaGetSymbolAddress(&p_coeff, g_coeff);
    cudaGetSymbolAddress(&p_wbh, g_wbh);
    cudaGetSymbolAddress(&p_wbl, g_wbl);
    const __nv_bfloat16* wbh = (const __nv_bfloat16*)p_wbh;
    const __nv_bfloat16* wbl = (const __nv_bfloat16*)p_wbl;

    cudaFuncSetAttribute(k_gemm_mma, cudaFuncAttributeMaxDynamicSharedMemorySize,
                         DYNSMEM);

    // weight split (all 4 matrices, once per launch)
    k_wconv<<<(4 * WTILE + 255) / 256, 256>>>(Wp[0], Wp[1], Wp[2], Wl);

    // degrees
    cudaMemsetAsync(p_dinv, 0, (size_t)M * sizeof(float));
    k_count<<<2048, 256>>>(ei, E);
    k_dinv<<<(M + 255) / 256, 256>>>(M);

    const int gemm_grid = (M + 127) / 128;
    const float* in = x;
    const float* cf = nullptr;
    for (int L = 0; L < 3; L++) {
        k_gemm_mma<<<gemm_grid, 256, DYNSMEM>>>(in, wbh + L * WTILE,
                                                wbl + L * WTILE,
                                                bp[L], cf, (float*)p_h, M);
        cudaMemsetAsync(p_acc, 0, (size_t)M * D * sizeof(float));
        k_edge<<<1536, 256>>>((const float*)p_h, ei, ea, Wep[L], bep[L], E);
        cudaMemsetAsync(p_stats, 0, 2 * D * sizeof(double));
        k_bnstats<<<1024, 128>>>(M);
        k_bncoeff<<<1, 128>>>(gp[L], btp[L], M);
        in = (const float*)p_acc;
        cf = (const float*)p_coeff;
    }
    k_gemm_mma<<<gemm_grid, 256, DYNSMEM>>>(in, wbh + 3 * WTILE, wbl + 3 * WTILE,
                                            bl, cf, (float*)d_out, M);
}

// round 9
// speedup vs baseline: 1.3652x; 1.1627x over previous
#include <cuda_runtime.h>
#include <cuda_bf16.h>
#include <cstdint>

#define D 128
#define NMAX 100000
#define EMAX 1600000
#define NBLK 98                         // ceil(NMAX/1024)
#define WTILE (128 * 128)
#define PITCH 272                       // smem row pitch in bytes (136 bf16)
#define ATILE (128 * PITCH)             // 34816 B per 128x128 bf16 tile
#define DYNSMEM (4 * ATILE)             // Ah, Al, Bh, Bl = 139264 B

// ---- scratch (static device globals; no allocation allowed) ----
__device__ float  g_h[(size_t)NMAX * D];     // GEMM out / edge gather src
__device__ float  g_acc[(size_t)NMAX * D];   // aggregation output
__device__ float  g_dinv[NMAX];              // deg^-0.5
__device__ double g_stats[2 * D];            // per-feature sum, sumsq
__device__ float  g_coeff[2 * D];            // BN fused mul, add
__device__ __align__(16) __nv_bfloat16 g_wbh[4 * WTILE];  // W^T hi (bf16)
__device__ __align__(16) __nv_bfloat16 g_wbl[4 * WTILE];  // W^T lo residual
// CSR-by-destination structures
__device__ int    g_colcnt[NMAX];
__device__ int    g_colptr[NMAX + 1];
__device__ int    g_cursor[NMAX];
__device__ int    g_blksum[NBLK + 1];
__device__ int    g_blkoff[NBLK + 1];
__device__ __align__(16) int4 g_epack[EMAX]; // {row, bits(a0), bits(a1), bits(a2)}

__device__ __forceinline__ uint32_t pack_bf2(__nv_bfloat16 lo, __nv_bfloat16 hi) {
    return ((uint32_t)__bfloat16_as_ushort(hi) << 16) |
           (uint32_t)__bfloat16_as_ushort(lo);
}

// ------------------------------------------------------------------
// Degree (by row, float -> dinv) + in-degree histogram (by col, int)
// ------------------------------------------------------------------
__global__ void k_count(const int* __restrict__ ei, int E) {
    for (int i = blockIdx.x * blockDim.x + threadIdx.x; i < E;
         i += gridDim.x * blockDim.x) {
        atomicAdd(&g_dinv[ei[i]], 1.0f);
        atomicAdd(&g_colcnt[ei[E + i]], 1);
    }
}

__global__ void k_dinv(int M) {
    int i = blockIdx.x * blockDim.x + threadIdx.x;
    if (i < M) g_dinv[i] = rsqrtf(g_dinv[i] + 1.0f);
}

// ---- 3-phase exclusive scan of colcnt -> colptr ----
__global__ void k_scan1(int M) {        // grid=NBLK, block=1024
    __shared__ int sm[1024];
    int tid = threadIdx.x;
    int i   = blockIdx.x * 1024 + tid;
    int v   = (i < M) ? g_colcnt[i] : 0;
    sm[tid] = v;
    __syncthreads();
    #pragma unroll
    for (int off = 1; off < 1024; off <<= 1) {
        int t = (tid >= off) ? sm[tid - off] : 0;
        __syncthreads();
        sm[tid] += t;
        __syncthreads();
    }
    if (i < M) g_colptr[i] = sm[tid] - v;   // block-local exclusive
    if (tid == 1023) g_blksum[blockIdx.x] = sm[1023];
}

__global__ void k_scan2(int nb, int E) { // 1 thread
    int run = 0;
    for (int b = 0; b < nb; b++) { g_blkoff[b] = run; run += g_blksum[b]; }
    g_colptr[NMAX] = E;                  // only index M used below is NMAX? no:
}

__global__ void k_scan3(int M, int E) {
    int i = blockIdx.x * blockDim.x + threadIdx.x;
    if (i < M) {
        int p = g_colptr[i] + g_blkoff[i >> 10];
        g_colptr[i] = p;
        g_cursor[i] = p;
    }
    if (i == 0) g_colptr[M] = E;        // correct sentinel for runtime M
}

// ---- fill packed CSR records ----
__global__ void k_fill(const int* __restrict__ ei,
                       const float* __restrict__ ea, int E) {
    for (int i = blockIdx.x * blockDim.x + threadIdx.x; i < E;
         i += gridDim.x * blockDim.x) {
        int r = ei[i], c = ei[E + i];
        int pos = atomicAdd(&g_cursor[c], 1);
        int4 p;
        p.x = r;
        p.y = __float_as_int(ea[3 * i + 0]);
        p.z = __float_as_int(ea[3 * i + 1]);
        p.w = __float_as_int(ea[3 * i + 2]);
        g_epack[pos] = p;
    }
}

// ------------------------------------------------------------------
// Weight conversion: Wt[n][k] = split_bf16(W[k][n]) for 4 matrices
// ------------------------------------------------------------------
__global__ void k_wconv(const float* __restrict__ W0, const float* __restrict__ W1,
                        const float* __restrict__ W2, const float* __restrict__ W3) {
    int i = blockIdx.x * blockDim.x + threadIdx.x;   // 0 .. 4*16384-1
    if (i >= 4 * WTILE) return;
    int m = i >> 14, r = i & (WTILE - 1);
    int n = r >> 7, k = r & 127;
    const float* W = (m == 0) ? W0 : (m == 1) ? W1 : (m == 2) ? W2 : W3;
    float v = W[k * 128 + n];
    __nv_bfloat16 h = __float2bfloat16_rn(v);
    g_wbh[i] = h;
    g_wbl[i] = __float2bfloat16_rn(v - __bfloat162float(h));
}

// ------------------------------------------------------------------
// Tensor-core split-bf16 GEMM via mma.sync.m16n8k16:
//   C[M,128] = act(A)[M,128] @ W[128,128] + bias
//   act(A) = coeff ? relu(A)*mul+add : A   (fused BN)
//   C = Ah@Bh + Ah@Bl + Al@Bh  (fp32 accumulators)
// ------------------------------------------------------------------
__global__ __launch_bounds__(256, 1)
void k_gemm_mma(const float* __restrict__ A,
                const __nv_bfloat16* __restrict__ Bh,
                const __nv_bfloat16* __restrict__ Bl,
                const float* __restrict__ bias,
                const float* __restrict__ coeff,   // nullable [mul|add]
                float* __restrict__ C, int M)
{
    extern __shared__ char dsm[];
    char* pAh = dsm;
    char* pAl = dsm + ATILE;
    char* pBh = dsm + 2 * ATILE;
    char* pBl = dsm + 3 * ATILE;
    __shared__ float s_bias[128], s_mul[128], s_add[128];

    const int tid  = threadIdx.x;
    const int warp = tid >> 5;
    const int lane = tid & 31;
    const int g    = lane >> 2;
    const int tig  = lane & 3;
    const int m0   = blockIdx.x * 128;
    const bool useBN = (coeff != nullptr);

    if (tid < 128) {
        s_bias[tid] = bias[tid];
        if (useBN) { s_mul[tid] = coeff[tid]; s_add[tid] = coeff[128 + tid]; }
    }
    __syncthreads();   // s_mul/s_add read by all threads below

    #pragma unroll
    for (int it = 0; it < 8; it++) {
        int q = it * 256 + tid;
        int row = q >> 4, c8 = (q & 15) << 3;
        *(uint4*)(pBh + row * PITCH + c8 * 2) = *(const uint4*)(Bh + row * 128 + c8);
        *(uint4*)(pBl + row * PITCH + c8 * 2) = *(const uint4*)(Bl + row * 128 + c8);
    }

    #pragma unroll
    for (int it = 0; it < 16; it++) {
        int q = it * 256 + tid;
        int row = q >> 5, c4 = (q & 31) << 2;
        int grow = m0 + row;
        float4 v = make_float4(0.f, 0.f, 0.f, 0.f);
        if (grow < M) v = *(const float4*)(A + (size_t)grow * 128 + c4);
        float vv[4] = {v.x, v.y, v.z, v.w};
        if (useBN) {
            #pragma unroll
            for (int j = 0; j < 4; j++)
                vv[j] = fmaxf(vv[j], 0.f) * s_mul[c4 + j] + s_add[c4 + j];
        }
        __nv_bfloat16 h[4], l[4];
        #pragma unroll
        for (int j = 0; j < 4; j++) {
            h[j] = __float2bfloat16_rn(vv[j]);
            l[j] = __float2bfloat16_rn(vv[j] - __bfloat162float(h[j]));
        }
        uint2 hw, lw;
        hw.x = pack_bf2(h[0], h[1]); hw.y = pack_bf2(h[2], h[3]);
        lw.x = pack_bf2(l[0], l[1]); lw.y = pack_bf2(l[2], l[3]);
        *(uint2*)(pAh + row * PITCH + c4 * 2) = hw;
        *(uint2*)(pAl + row * PITCH + c4 * 2) = lw;
    }
    __syncthreads();

    float acc[16][4];
    #pragma unroll
    for (int nt = 0; nt < 16; nt++)
        #pragma unroll
        for (int j = 0; j < 4; j++) acc[nt][j] = 0.0f;

    const int arow = warp * 16;
    #pragma unroll
    for (int p = 0; p < 3; p++) {
        const char* As = (p == 2) ? pAl : pAh;
        const char* Bs = (p == 1) ? pBl : pBh;
        uint32_t a[8][4];
        #pragma unroll
        for (int k8 = 0; k8 < 8; k8++) {
            uint32_t base = (uint32_t)(arow + g) * PITCH + (uint32_t)k8 * 32 + 4u * tig;
            a[k8][0] = *(const uint32_t*)(As + base);
            a[k8][1] = *(const uint32_t*)(As + base + 8 * PITCH);
            a[k8][2] = *(const uint32_t*)(As + base + 16);
            a[k8][3] = *(const uint32_t*)(As + base + 8 * PITCH + 16);
        }
        #pragma unroll
        for (int nt = 0; nt < 16; nt++) {
            uint32_t brow = (uint32_t)(nt * 8 + g) * PITCH + 4u * tig;
            #pragma unroll
            for (int k8 = 0; k8 < 8; k8++) {
                uint32_t b0 = *(const uint32_t*)(Bs + brow + k8 * 32);
                uint32_t b1 = *(const uint32_t*)(Bs + brow + k8 * 32 + 16);
                asm volatile(
                    "mma.sync.aligned.m16n8k16.row.col.f32.bf16.bf16.f32 "
                    "{%0,%1,%2,%3}, {%4,%5,%6,%7}, {%8,%9}, {%0,%1,%2,%3};"
                    : "+f"(acc[nt][0]), "+f"(acc[nt][1]),
                      "+f"(acc[nt][2]), "+f"(acc[nt][3])
                    : "r"(a[k8][0]), "r"(a[k8][1]), "r"(a[k8][2]), "r"(a[k8][3]),
                      "r"(b0), "r"(b1));
            }
        }
    }

    const int r0 = m0 + arow + g;
    const int r1 = r0 + 8;
    #pragma unroll
    for (int nt = 0; nt < 16; nt++) {
        int col = nt * 8 + tig * 2;
        float bx = s_bias[col], by = s_bias[col + 1];
        if (r0 < M) {
            float2 o = make_float2(acc[nt][0] + bx, acc[nt][1] + by);
            *(float2*)(C + (size_t)r0 * 128 + col) = o;
        }
        if (r1 < M) {
            float2 o = make_float2(acc[nt][2] + bx, acc[nt][3] + by);
            *(float2*)(C + (size_t)r1 * 128 + col) = o;
        }
    }
}

// ------------------------------------------------------------------
// CSR aggregation: one warp per destination node (lane owns 4 feats).
//   acc[n] = sum_{e: col(e)=n} relu(h[row] + ea@We + be) * dinv[row]*dinv[n]
// Gather-only (no atomics); single coalesced write per node.
// ------------------------------------------------------------------
__global__ __launch_bounds__(256)
void k_aggr(const float* __restrict__ h, const float* __restrict__ We,
            const float* __restrict__ be, int M)
{
    const int lane = threadIdx.x & 31;
    const int warp = (blockIdx.x * blockDim.x + threadIdx.x) >> 5;
    const int nw   = (gridDim.x * blockDim.x) >> 5;
    const int f    = lane << 2;

    const float4 w0 = *(const float4*)(We + f);
    const float4 w1 = *(const float4*)(We + D + f);
    const float4 w2 = *(const float4*)(We + 2 * D + f);
    const float4 b4 = *(const float4*)(be + f);

    for (int n = warp; n < M; n += nw) {
        const int beg = g_colptr[n];
        const int end = g_colptr[n + 1];
        const float dcn = g_dinv[n];
        float4 acc = make_float4(0.f, 0.f, 0.f, 0.f);

        int pos = beg;
        for (; pos + 2 <= end; pos += 2) {
            int4 e0 = g_epack[pos];
            int4 e1 = g_epack[pos + 1];
            float nr0 = dcn * g_dinv[e0.x];
            float nr1 = dcn * g_dinv[e1.x];
            float4 h0 = *(const float4*)(h + (size_t)e0.x * D + f);
            float4 h1 = *(const float4*)(h + (size_t)e1.x * D + f);
            float a00 = __int_as_float(e0.y), a01 = __int_as_float(e0.z),
                  a02 = __int_as_float(e0.w);
            float a10 = __int_as_float(e1.y), a11 = __int_as_float(e1.z),
                  a12 = __int_as_float(e1.w);
            acc.x += fmaxf(h0.x + b4.x + a00*w0.x + a01*w1.x + a02*w2.x, 0.f) * nr0
                   + fmaxf(h1.x + b4.x + a10*w0.x + a11*w1.x + a12*w2.x, 0.f) * nr1;
            acc.y += fmaxf(h0.y + b4.y + a00*w0.y + a01*w1.y + a02*w2.y, 0.f) * nr0
                   + fmaxf(h1.y + b4.y + a10*w0.y + a11*w1.y + a12*w2.y, 0.f) * nr1;
            acc.z += fmaxf(h0.z + b4.z + a00*w0.z + a01*w1.z + a02*w2.z, 0.f) * nr0
                   + fmaxf(h1.z + b4.z + a10*w0.z + a11*w1.z + a12*w2.z, 0.f) * nr1;
            acc.w += fmaxf(h0.w + b4.w + a00*w0.w + a01*w1.w + a02*w2.w, 0.f) * nr0
                   + fmaxf(h1.w + b4.w + a10*w0.w + a11*w1.w + a12*w2.w, 0.f) * nr1;
        }
        if (pos < end) {
            int4 e0 = g_epack[pos];
            float nr0 = dcn * g_dinv[e0.x];
            float4 h0 = *(const float4*)(h + (size_t)e0.x * D + f);
            float a00 = __int_as_float(e0.y), a01 = __int_as_float(e0.z),
                  a02 = __int_as_float(e0.w);
            acc.x += fmaxf(h0.x + b4.x + a00*w0.x + a01*w1.x + a02*w2.x, 0.f) * nr0;
            acc.y += fmaxf(h0.y + b4.y + a00*w0.y + a01*w1.y + a02*w2.y, 0.f) * nr0;
            acc.z += fmaxf(h0.z + b4.z + a00*w0.z + a01*w1.z + a02*w2.z, 0.f) * nr0;
            acc.w += fmaxf(h0.w + b4.w + a00*w0.w + a01*w1.w + a02*w2.w, 0.f) * nr0;
        }
        *(float4*)(g_acc + (size_t)n * D + f) = acc;
    }
}

// ------------------------------------------------------------------
// BN stats over relu(acc): per-feature sum & sumsq (double accum)
// ------------------------------------------------------------------
__global__ void k_bnstats(int M) {
    const int f = threadIdx.x;
    double s = 0.0, s2 = 0.0;
    for (int r = blockIdx.x; r < M; r += gridDim.x) {
        float v = fmaxf(g_acc[(size_t)r * D + f], 0.0f);
        s  += (double)v;
        s2 += (double)v * (double)v;
    }
    atomicAdd(&g_stats[f], s);
    atomicAdd(&g_stats[D + f], s2);
}

__global__ void k_bncoeff(const float* __restrict__ g,
                          const float* __restrict__ bt, int M) {
    const int f = threadIdx.x;
    double mean = g_stats[f] / (double)M;
    double var  = g_stats[D + f] / (double)M - mean * mean;
    float mul = g[f] * rsqrtf((float)var + 1e-5f);
    g_coeff[f]     = mul;
    g_coeff[D + f] = bt[f] - (float)mean * mul;
}

// ------------------------------------------------------------------
extern "C" void kernel_launch(void* const* d_in, const int* in_sizes, int n_in,
                              void* d_out, int out_size)
{
    const float* x  = (const float*)d_in[0];
    const int*   ei = (const int*)d_in[1];
    const float* ea = (const float*)d_in[2];
    const float* Wp[3]  = {(const float*)d_in[3],  (const float*)d_in[9],  (const float*)d_in[15]};
    const float* bp[3]  = {(const float*)d_in[4],  (const float*)d_in[10], (const float*)d_in[16]};
    const float* Wep[3] = {(const float*)d_in[5],  (const float*)d_in[11], (const float*)d_in[17]};
    const float* bep[3] = {(const float*)d_in[6],  (const float*)d_in[12], (const float*)d_in[18]};
    const float* gp[3]  = {(const float*)d_in[7],  (const float*)d_in[13], (const float*)d_in[19]};
    const float* btp[3] = {(const float*)d_in[8],  (const float*)d_in[14], (const float*)d_in[20]};
    const float* Wl = (const float*)d_in[21];
    const float* bl = (const float*)d_in[22];

    const int M = in_sizes[0] / D;
    const int E = in_sizes[1] / 2;

    // Resolve __device__ symbols via the runtime (GB300 ATS pitfall).
    void *p_h, *p_acc, *p_dinv, *p_stats, *p_coeff, *p_wbh, *p_wbl, *p_colcnt;
    cudaGetSymbolAddress(&p_h, g_h);
    cudaGetSymbolAddress(&p_acc, g_acc);
    cudaGetSymbolAddress(&p_dinv, g_dinv);
    cudaGetSymbolAddress(&p_stats, g_stats);
    cudaGetSymbolAddress(&p_coeff, g_coeff);
    cudaGetSymbolAddress(&p_wbh, g_wbh);
    cudaGetSymbolAddress(&p_wbl, g_wbl);
    cudaGetSymbolAddress(&p_colcnt, g_colcnt);
    const __nv_bfloat16* wbh = (const __nv_bfloat16*)p_wbh;
    const __nv_bfloat16* wbl = (const __nv_bfloat16*)p_wbl;

    cudaFuncSetAttribute(k_gemm_mma, cudaFuncAttributeMaxDynamicSharedMemorySize,
                         DYNSMEM);

    // weight split (once per launch)
    k_wconv<<<(4 * WTILE + 255) / 256, 256>>>(Wp[0], Wp[1], Wp[2], Wl);

    // degrees + CSR build (once per launch, reused for all 3 layers)
    cudaMemsetAsync(p_dinv, 0, (size_t)M * sizeof(float));
    cudaMemsetAsync(p_colcnt, 0, (size_t)M * sizeof(int));
    k_count<<<2048, 256>>>(ei, E);
    k_dinv<<<(M + 255) / 256, 256>>>(M);
    const int nb = (M + 1023) / 1024;
    k_scan1<<<nb, 1024>>>(M);
    k_scan2<<<1, 1>>>(nb, E);
    k_scan3<<<(M + 255) / 256, 256>>>(M, E);
    k_fill<<<2048, 256>>>(ei, ea, E);

    const int gemm_grid = (M + 127) / 128;
    const float* in = x;
    const float* cf = nullptr;
    for (int L = 0; L < 3; L++) {
        k_gemm_mma<<<gemm_grid, 256, DYNSMEM>>>(in, wbh + L * WTILE,
                                                wbl + L * WTILE,
                                                bp[L], cf, (float*)p_h, M);
        k_aggr<<<(M * 32 + 255) / 256, 256>>>((const float*)p_h,
                                              Wep[L], bep[L], M);
        cudaMemsetAsync(p_stats, 0, 2 * D * sizeof(double));
        k_bnstats<<<1024, 128>>>(M);
        k_bncoeff<<<1, 128>>>(gp[L], btp[L], M);
        in = (const float*)p_acc;
        cf = (const float*)p_coeff;
    }
    k_gemm_mma<<<gemm_grid, 256, DYNSMEM>>>(in, wbh + 3 * WTILE, wbl + 3 * WTILE,
                                            bl, cf, (float*)d_out, M);
}

// round 10
// speedup vs baseline: 1.7545x; 1.2852x over previous
#include <cuda_runtime.h>
#include <cuda_bf16.h>
#include <cstdint>

#define D 128
#define NMAX 100000
#define EMAX 1600000
#define NBLK 98                         // ceil(NMAX/1024)
#define WTILE (128 * 128)
#define PITCH 272                       // smem row pitch in bytes (136 bf16)
#define ATILE (128 * PITCH)             // 34816 B per 128x128 bf16 tile
#define DYNSMEM (4 * ATILE)             // Ah, Al, Bh, Bl = 139264 B

// ---- scratch (static device globals; no allocation allowed) ----
__device__ float  g_h[(size_t)NMAX * D];     // GEMM out / edge gather src
__device__ float  g_acc[(size_t)NMAX * D];   // aggregation output
__device__ float  g_dinv[NMAX];              // deg^-0.5
__device__ double g_stats[2 * D];            // per-feature sum, sumsq
__device__ float  g_coeff[2 * D];            // BN fused mul, add
__device__ __align__(16) __nv_bfloat16 g_wbh[4 * WTILE];  // W^T hi (bf16)
__device__ __align__(16) __nv_bfloat16 g_wbl[4 * WTILE];  // W^T lo residual
// CSR-by-destination structures
__device__ int    g_colcnt[NMAX];
__device__ int    g_colptr[NMAX + 1];
__device__ int    g_cursor[NMAX];
__device__ int    g_blksum[NBLK + 1];
__device__ int    g_blkoff[NBLK + 1];
__device__ __align__(16) int4 g_epack[EMAX]; // {row, bits(a0), bits(a1), bits(a2)}

__device__ __forceinline__ uint32_t pack_bf2(__nv_bfloat16 lo, __nv_bfloat16 hi) {
    return ((uint32_t)__bfloat16_as_ushort(hi) << 16) |
           (uint32_t)__bfloat16_as_ushort(lo);
}

// ------------------------------------------------------------------
// Degree (by row, float -> dinv) + in-degree histogram (by col, int)
// ------------------------------------------------------------------
__global__ void k_count(const int* __restrict__ ei, int E) {
    for (int i = blockIdx.x * blockDim.x + threadIdx.x; i < E;
         i += gridDim.x * blockDim.x) {
        atomicAdd(&g_dinv[ei[i]], 1.0f);
        atomicAdd(&g_colcnt[ei[E + i]], 1);
    }
}

__global__ void k_dinv(int M) {
    int i = blockIdx.x * blockDim.x + threadIdx.x;
    if (i < M) g_dinv[i] = rsqrtf(g_dinv[i] + 1.0f);
}

// ---- 3-phase exclusive scan of colcnt -> colptr ----
__global__ void k_scan1(int M) {        // grid=NBLK, block=1024
    __shared__ int sm[1024];
    int tid = threadIdx.x;
    int i   = blockIdx.x * 1024 + tid;
    int v   = (i < M) ? g_colcnt[i] : 0;
    sm[tid] = v;
    __syncthreads();
    #pragma unroll
    for (int off = 1; off < 1024; off <<= 1) {
        int t = (tid >= off) ? sm[tid - off] : 0;
        __syncthreads();
        sm[tid] += t;
        __syncthreads();
    }
    if (i < M) g_colptr[i] = sm[tid] - v;   // block-local exclusive
    if (tid == 1023) g_blksum[blockIdx.x] = sm[1023];
}

// parallel scan of per-block sums (was 1-thread latency chain)
__global__ void k_scan2(int nb) {       // 1 block x 128 threads
    __shared__ int sm[128];
    int tid = threadIdx.x;
    int v = (tid < nb) ? g_blksum[tid] : 0;
    sm[tid] = v;
    __syncthreads();
    #pragma unroll
    for (int off = 1; off < 128; off <<= 1) {
        int t = (tid >= off) ? sm[tid - off] : 0;
        __syncthreads();
        sm[tid] += t;
        __syncthreads();
    }
    if (tid <= nb) g_blkoff[tid] = sm[tid] - v;   // exclusive
}

__global__ void k_scan3(int M, int E) {
    int i = blockIdx.x * blockDim.x + threadIdx.x;
    if (i < M) {
        int p = g_colptr[i] + g_blkoff[i >> 10];
        g_colptr[i] = p;
        g_cursor[i] = p;
    }
    if (i == 0) g_colptr[M] = E;
}

// ---- fill packed CSR records ----
__global__ void k_fill(const int* __restrict__ ei,
                       const float* __restrict__ ea, int E) {
    for (int i = blockIdx.x * blockDim.x + threadIdx.x; i < E;
         i += gridDim.x * blockDim.x) {
        int r = ei[i], c = ei[E + i];
        int pos = atomicAdd(&g_cursor[c], 1);
        int4 p;
        p.x = r;
        p.y = __float_as_int(ea[3 * i + 0]);
        p.z = __float_as_int(ea[3 * i + 1]);
        p.w = __float_as_int(ea[3 * i + 2]);
        g_epack[pos] = p;
    }
}

// ------------------------------------------------------------------
// Weight conversion: Wt[n][k] = split_bf16(W[k][n]) for 4 matrices
// ------------------------------------------------------------------
__global__ void k_wconv(const float* __restrict__ W0, const float* __restrict__ W1,
                        const float* __restrict__ W2, const float* __restrict__ W3) {
    int i = blockIdx.x * blockDim.x + threadIdx.x;
    if (i >= 4 * WTILE) return;
    int m = i >> 14, r = i & (WTILE - 1);
    int n = r >> 7, k = r & 127;
    const float* W = (m == 0) ? W0 : (m == 1) ? W1 : (m == 2) ? W2 : W3;
    float v = W[k * 128 + n];
    __nv_bfloat16 h = __float2bfloat16_rn(v);
    g_wbh[i] = h;
    g_wbl[i] = __float2bfloat16_rn(v - __bfloat162float(h));
}

// ------------------------------------------------------------------
// Tensor-core split-bf16 GEMM via mma.sync.m16n8k16:
//   C[M,128] = act(A)[M,128] @ W[128,128] + bias
//   act(A) = coeff ? relu(A)*mul+add : A   (fused BN)
//   C = (Ah + Al)@Bh + Ah@Bl  (fp32 accumulators, 2 passes sharing B)
// k8-outer / nt-inner: 16 independent HMMAs per acc reuse, ~4-8 live
// A-fragment regs (R8 had a[8][4] prefetch + nt-outer -> 255 regs, spills).
// ------------------------------------------------------------------
__global__ __launch_bounds__(256, 1)
void k_gemm_mma(const float* __restrict__ A,
                const __nv_bfloat16* __restrict__ Bh,
                const __nv_bfloat16* __restrict__ Bl,
                const float* __restrict__ bias,
                const float* __restrict__ coeff,   // nullable [mul|add]
                float* __restrict__ C, int M)
{
    extern __shared__ char dsm[];
    char* pAh = dsm;
    char* pAl = dsm + ATILE;
    char* pBh = dsm + 2 * ATILE;
    char* pBl = dsm + 3 * ATILE;
    __shared__ float s_bias[128], s_mul[128], s_add[128];

    const int tid  = threadIdx.x;
    const int warp = tid >> 5;
    const int lane = tid & 31;
    const int g    = lane >> 2;
    const int tig  = lane & 3;
    const int m0   = blockIdx.x * 128;
    const bool useBN = (coeff != nullptr);

    if (tid < 128) {
        s_bias[tid] = bias[tid];
        if (useBN) { s_mul[tid] = coeff[tid]; s_add[tid] = coeff[128 + tid]; }
    }
    __syncthreads();   // s_mul/s_add read by all threads below

    #pragma unroll
    for (int it = 0; it < 8; it++) {
        int q = it * 256 + tid;
        int row = q >> 4, c8 = (q & 15) << 3;
        *(uint4*)(pBh + row * PITCH + c8 * 2) = *(const uint4*)(Bh + row * 128 + c8);
        *(uint4*)(pBl + row * PITCH + c8 * 2) = *(const uint4*)(Bl + row * 128 + c8);
    }

    #pragma unroll
    for (int it = 0; it < 16; it++) {
        int q = it * 256 + tid;
        int row = q >> 5, c4 = (q & 31) << 2;
        int grow = m0 + row;
        float4 v = make_float4(0.f, 0.f, 0.f, 0.f);
        if (grow < M) v = *(const float4*)(A + (size_t)grow * 128 + c4);
        float vv[4] = {v.x, v.y, v.z, v.w};
        if (useBN) {
            #pragma unroll
            for (int j = 0; j < 4; j++)
                vv[j] = fmaxf(vv[j], 0.f) * s_mul[c4 + j] + s_add[c4 + j];
        }
        __nv_bfloat16 h[4], l[4];
        #pragma unroll
        for (int j = 0; j < 4; j++) {
            h[j] = __float2bfloat16_rn(vv[j]);
            l[j] = __float2bfloat16_rn(vv[j] - __bfloat162float(h[j]));
        }
        uint2 hw, lw;
        hw.x = pack_bf2(h[0], h[1]); hw.y = pack_bf2(h[2], h[3]);
        lw.x = pack_bf2(l[0], l[1]); lw.y = pack_bf2(l[2], l[3]);
        *(uint2*)(pAh + row * PITCH + c4 * 2) = hw;
        *(uint2*)(pAl + row * PITCH + c4 * 2) = lw;
    }
    __syncthreads();

    float acc[16][4];
    #pragma unroll
    for (int nt = 0; nt < 16; nt++)
        #pragma unroll
        for (int j = 0; j < 4; j++) acc[nt][j] = 0.0f;

    const int arow = warp * 16;

    // ---- pass 1: (Ah + Al) @ Bh ----
    #pragma unroll
    for (int k8 = 0; k8 < 8; k8++) {
        uint32_t abase = (uint32_t)(arow + g) * PITCH + (uint32_t)k8 * 32 + 4u * tig;
        uint32_t ah[4], al[4];
        ah[0] = *(const uint32_t*)(pAh + abase);
        ah[1] = *(const uint32_t*)(pAh + abase + 8 * PITCH);
        ah[2] = *(const uint32_t*)(pAh + abase + 16);
        ah[3] = *(const uint32_t*)(pAh + abase + 8 * PITCH + 16);
        al[0] = *(const uint32_t*)(pAl + abase);
        al[1] = *(const uint32_t*)(pAl + abase + 8 * PITCH);
        al[2] = *(const uint32_t*)(pAl + abase + 16);
        al[3] = *(const uint32_t*)(pAl + abase + 8 * PITCH + 16);
        #pragma unroll
        for (int nt = 0; nt < 16; nt++) {
            uint32_t boff = (uint32_t)(nt * 8 + g) * PITCH + 4u * tig + k8 * 32;
            uint32_t b0 = *(const uint32_t*)(pBh + boff);
            uint32_t b1 = *(const uint32_t*)(pBh + boff + 16);
            asm volatile(
                "mma.sync.aligned.m16n8k16.row.col.f32.bf16.bf16.f32 "
                "{%0,%1,%2,%3}, {%4,%5,%6,%7}, {%8,%9}, {%0,%1,%2,%3};"
                : "+f"(acc[nt][0]), "+f"(acc[nt][1]),
                  "+f"(acc[nt][2]), "+f"(acc[nt][3])
                : "r"(ah[0]), "r"(ah[1]), "r"(ah[2]), "r"(ah[3]),
                  "r"(b0), "r"(b1));
            asm volatile(
                "mma.sync.aligned.m16n8k16.row.col.f32.bf16.bf16.f32 "
                "{%0,%1,%2,%3}, {%4,%5,%6,%7}, {%8,%9}, {%0,%1,%2,%3};"
                : "+f"(acc[nt][0]), "+f"(acc[nt][1]),
                  "+f"(acc[nt][2]), "+f"(acc[nt][3])
                : "r"(al[0]), "r"(al[1]), "r"(al[2]), "r"(al[3]),
                  "r"(b0), "r"(b1));
        }
    }
    // ---- pass 2: Ah @ Bl ----
    #pragma unroll
    for (int k8 = 0; k8 < 8; k8++) {
        uint32_t abase = (uint32_t)(arow + g) * PITCH + (uint32_t)k8 * 32 + 4u * tig;
        uint32_t ah[4];
        ah[0] = *(const uint32_t*)(pAh + abase);
        ah[1] = *(const uint32_t*)(pAh + abase + 8 * PITCH);
        ah[2] = *(const uint32_t*)(pAh + abase + 16);
        ah[3] = *(const uint32_t*)(pAh + abase + 8 * PITCH + 16);
        #pragma unroll
        for (int nt = 0; nt < 16; nt++) {
            uint32_t boff = (uint32_t)(nt * 8 + g) * PITCH + 4u * tig + k8 * 32;
            uint32_t b0 = *(const uint32_t*)(pBl + boff);
            uint32_t b1 = *(const uint32_t*)(pBl + boff + 16);
            asm volatile(
                "mma.sync.aligned.m16n8k16.row.col.f32.bf16.bf16.f32 "
                "{%0,%1,%2,%3}, {%4,%5,%6,%7}, {%8,%9}, {%0,%1,%2,%3};"
                : "+f"(acc[nt][0]), "+f"(acc[nt][1]),
                  "+f"(acc[nt][2]), "+f"(acc[nt][3])
                : "r"(ah[0]), "r"(ah[1]), "r"(ah[2]), "r"(ah[3]),
                  "r"(b0), "r"(b1));
        }
    }

    const int r0 = m0 + arow + g;
    const int r1 = r0 + 8;
    #pragma unroll
    for (int nt = 0; nt < 16; nt++) {
        int col = nt * 8 + tig * 2;
        float bx = s_bias[col], by = s_bias[col + 1];
        if (r0 < M) {
            float2 o = make_float2(acc[nt][0] + bx, acc[nt][1] + by);
            *(float2*)(C + (size_t)r0 * 128 + col) = o;
        }
        if (r1 < M) {
            float2 o = make_float2(acc[nt][2] + bx, acc[nt][3] + by);
            *(float2*)(C + (size_t)r1 * 128 + col) = o;
        }
    }
}

// ------------------------------------------------------------------
// CSR aggregation + fused BN statistics.
// One warp per destination node (lane owns 4 feats), warps loop nodes.
//   acc[n] = sum_{e: col(e)=n} relu(h[row] + ea@We + be) * dinv[row]*dinv[n]
// Per-lane fp32 partials of sum/sumsq over relu(acc), block-reduced via
// smem double atomics, one global double-atomic set per block.
// ------------------------------------------------------------------
__global__ __launch_bounds__(256)
void k_aggr(const float* __restrict__ h, const float* __restrict__ We,
            const float* __restrict__ be, int M)
{
    __shared__ double sm_s[128], sm_s2[128];
    const int tid  = threadIdx.x;
    const int lane = tid & 31;
    const int warp = (blockIdx.x * blockDim.x + tid) >> 5;
    const int nw   = (gridDim.x * blockDim.x) >> 5;
    const int f    = lane << 2;

    if (tid < 128) { sm_s[tid] = 0.0; sm_s2[tid] = 0.0; }
    __syncthreads();

    const float4 w0 = *(const float4*)(We + f);
    const float4 w1 = *(const float4*)(We + D + f);
    const float4 w2 = *(const float4*)(We + 2 * D + f);
    const float4 b4 = *(const float4*)(be + f);

    float ps[4]  = {0.f, 0.f, 0.f, 0.f};
    float ps2[4] = {0.f, 0.f, 0.f, 0.f};

    for (int n = warp; n < M; n += nw) {
        const int beg = g_colptr[n];
        const int end = g_colptr[n + 1];
        const float dcn = g_dinv[n];
        float4 acc = make_float4(0.f, 0.f, 0.f, 0.f);

        int pos = beg;
        for (; pos + 2 <= end; pos += 2) {
            int4 e0 = g_epack[pos];
            int4 e1 = g_epack[pos + 1];
            float nr0 = dcn * g_dinv[e0.x];
            float nr1 = dcn * g_dinv[e1.x];
            float4 h0 = *(const float4*)(h + (size_t)e0.x * D + f);
            float4 h1 = *(const float4*)(h + (size_t)e1.x * D + f);
            float a00 = __int_as_float(e0.y), a01 = __int_as_float(e0.z),
                  a02 = __int_as_float(e0.w);
            float a10 = __int_as_float(e1.y), a11 = __int_as_float(e1.z),
                  a12 = __int_as_float(e1.w);
            acc.x += fmaxf(h0.x + b4.x + a00*w0.x + a01*w1.x + a02*w2.x, 0.f) * nr0
                   + fmaxf(h1.x + b4.x + a10*w0.x + a11*w1.x + a12*w2.x, 0.f) * nr1;
            acc.y += fmaxf(h0.y + b4.y + a00*w0.y + a01*w1.y + a02*w2.y, 0.f) * nr0
                   + fmaxf(h1.y + b4.y + a10*w0.y + a11*w1.y + a12*w2.y, 0.f) * nr1;
            acc.z += fmaxf(h0.z + b4.z + a00*w0.z + a01*w1.z + a02*w2.z, 0.f) * nr0
                   + fmaxf(h1.z + b4.z + a10*w0.z + a11*w1.z + a12*w2.z, 0.f) * nr1;
            acc.w += fmaxf(h0.w + b4.w + a00*w0.w + a01*w1.w + a02*w2.w, 0.f) * nr0
                   + fmaxf(h1.w + b4.w + a10*w0.w + a11*w1.w + a12*w2.w, 0.f) * nr1;
        }
        if (pos < end) {
            int4 e0 = g_epack[pos];
            float nr0 = dcn * g_dinv[e0.x];
            float4 h0 = *(const float4*)(h + (size_t)e0.x * D + f);
            float a00 = __int_as_float(e0.y), a01 = __int_as_float(e0.z),
                  a02 = __int_as_float(e0.w);
            acc.x += fmaxf(h0.x + b4.x + a00*w0.x + a01*w1.x + a02*w2.x, 0.f) * nr0;
            acc.y += fmaxf(h0.y + b4.y + a00*w0.y + a01*w1.y + a02*w2.y, 0.f) * nr0;
            acc.z += fmaxf(h0.z + b4.z + a00*w0.z + a01*w1.z + a02*w2.z, 0.f) * nr0;
            acc.w += fmaxf(h0.w + b4.w + a00*w0.w + a01*w1.w + a02*w2.w, 0.f) * nr0;
        }
        *(float4*)(g_acc + (size_t)n * D + f) = acc;

        // fused BN stats over relu(acc)
        float r0 = fmaxf(acc.x, 0.f), r1 = fmaxf(acc.y, 0.f);
        float r2 = fmaxf(acc.z, 0.f), r3 = fmaxf(acc.w, 0.f);
        ps[0] += r0; ps2[0] += r0 * r0;
        ps[1] += r1; ps2[1] += r1 * r1;
        ps[2] += r2; ps2[2] += r2 * r2;
        ps[3] += r3; ps2[3] += r3 * r3;
    }

    #pragma unroll
    for (int j = 0; j < 4; j++) {
        atomicAdd(&sm_s[f + j],  (double)ps[j]);
        atomicAdd(&sm_s2[f + j], (double)ps2[j]);
    }
    __syncthreads();
    if (tid < 128) {
        atomicAdd(&g_stats[tid],     sm_s[tid]);
        atomicAdd(&g_stats[D + tid], sm_s2[tid]);
    }
}

__global__ void k_bncoeff(const float* __restrict__ g,
                          const float* __restrict__ bt, int M) {
    const int f = threadIdx.x;
    double mean = g_stats[f] / (double)M;
    double var  = g_stats[D + f] / (double)M - mean * mean;
    float mul = g[f] * rsqrtf((float)var + 1e-5f);
    g_coeff[f]     = mul;
    g_coeff[D + f] = bt[f] - (float)mean * mul;
}

// ------------------------------------------------------------------
extern "C" void kernel_launch(void* const* d_in, const int* in_sizes, int n_in,
                              void* d_out, int out_size)
{
    const float* x  = (const float*)d_in[0];
    const int*   ei = (const int*)d_in[1];
    const float* ea = (const float*)d_in[2];
    const float* Wp[3]  = {(const float*)d_in[3],  (const float*)d_in[9],  (const float*)d_in[15]};
    const float* bp[3]  = {(const float*)d_in[4],  (const float*)d_in[10], (const float*)d_in[16]};
    const float* Wep[3] = {(const float*)d_in[5],  (const float*)d_in[11], (const float*)d_in[17]};
    const float* bep[3] = {(const float*)d_in[6],  (const float*)d_in[12], (const float*)d_in[18]};
    const float* gp[3]  = {(const float*)d_in[7],  (const float*)d_in[13], (const float*)d_in[19]};
    const float* btp[3] = {(const float*)d_in[8],  (const float*)d_in[14], (const float*)d_in[20]};
    const float* Wl = (const float*)d_in[21];
    const float* bl = (const float*)d_in[22];

    const int M = in_sizes[0] / D;
    const int E = in_sizes[1] / 2;

    // Resolve __device__ symbols via the runtime (GB300 ATS pitfall).
    void *p_h, *p_acc, *p_dinv, *p_stats, *p_coeff, *p_wbh, *p_wbl, *p_colcnt;
    cudaGetSymbolAddress(&p_h, g_h);
    cudaGetSymbolAddress(&p_acc, g_acc);
    cudaGetSymbolAddress(&p_dinv, g_dinv);
    cudaGetSymbolAddress(&p_stats, g_stats);
    cudaGetSymbolAddress(&p_coeff, g_coeff);
    cudaGetSymbolAddress(&p_wbh, g_wbh);
    cudaGetSymbolAddress(&p_wbl, g_wbl);
    cudaGetSymbolAddress(&p_colcnt, g_colcnt);
    const __nv_bfloat16* wbh = (const __nv_bfloat16*)p_wbh;
    const __nv_bfloat16* wbl = (const __nv_bfloat16*)p_wbl;

    cudaFuncSetAttribute(k_gemm_mma, cudaFuncAttributeMaxDynamicSharedMemorySize,
                         DYNSMEM);

    // weight split (once per launch)
    k_wconv<<<(4 * WTILE + 255) / 256, 256>>>(Wp[0], Wp[1], Wp[2], Wl);

    // degrees + CSR build (once per launch, reused for all 3 layers)
    cudaMemsetAsync(p_dinv, 0, (size_t)M * sizeof(float));
    cudaMemsetAsync(p_colcnt, 0, (size_t)M * sizeof(int));
    k_count<<<2048, 256>>>(ei, E);
    k_dinv<<<(M + 255) / 256, 256>>>(M);
    const int nb = (M + 1023) / 1024;
    k_scan1<<<nb, 1024>>>(M);
    k_scan2<<<1, 128>>>(nb);
    k_scan3<<<(M + 255) / 256, 256>>>(M, E);
    k_fill<<<2048, 256>>>(ei, ea, E);

    const int gemm_grid = (M + 127) / 128;
    const float* in = x;
    const float* cf = nullptr;
    for (int L = 0; L < 3; L++) {
        k_gemm_mma<<<gemm_grid, 256, DYNSMEM>>>(in, wbh + L * WTILE,
                                                wbl + L * WTILE,
                                                bp[L], cf, (float*)p_h, M);
        cudaMemsetAsync(p_stats, 0, 2 * D * sizeof(double));
        k_aggr<<<2048, 256>>>((const float*)p_h, Wep[L], bep[L], M);
        k_bncoeff<<<1, 128>>>(gp[L], btp[L], M);
        in = (const float*)p_acc;
        cf = (const float*)p_coeff;
    }
    k_gemm_mma<<<gemm_grid, 256, DYNSMEM>>>(in, wbh + 3 * WTILE, wbl + 3 * WTILE,
                                            bl, cf, (float*)d_out, M);
}

// round 11
// speedup vs baseline: 1.8629x; 1.0618x over previous
#include <cuda_runtime.h>
#include <cuda_bf16.h>
#include <cstdint>

#define D 128
#define NMAX 100000
#define EMAX 1600000
#define NBLK 98                         // ceil(NMAX/1024)
#define WTILE (128 * 128)
#define PITCH 272                       // smem row pitch in bytes (136 bf16)
#define ATILE (128 * PITCH)             // 34816 B per 128x128 bf16 tile
#define DYNSMEM (4 * ATILE)             // Ah, Al, Bh, Bl = 139264 B

// ---- scratch (static device globals; no allocation allowed) ----
__device__ float  g_h[(size_t)NMAX * D];     // GEMM out / edge gather src
__device__ float  g_acc[(size_t)NMAX * D];   // aggregation output
__device__ float  g_dinv[NMAX];              // deg^-0.5
__device__ double g_stats[2 * D];            // per-feature sum, sumsq
__device__ float  g_coeff[2 * D];            // BN fused mul, add
__device__ __align__(16) __nv_bfloat16 g_wbh[4 * WTILE];  // W^T hi (bf16)
__device__ __align__(16) __nv_bfloat16 g_wbl[4 * WTILE];  // W^T lo residual
// CSR-by-destination structures
__device__ int    g_colcnt[NMAX];
__device__ int    g_colptr[NMAX + 1];
__device__ int    g_cursor[NMAX];
__device__ int    g_blksum[NBLK + 1];
__device__ int    g_blkoff[NBLK + 1];
__device__ __align__(16) int4 g_epack[EMAX]; // {row, bits(a0), bits(a1), bits(a2)}

__device__ __forceinline__ uint32_t pack_bf2(__nv_bfloat16 lo, __nv_bfloat16 hi) {
    return ((uint32_t)__bfloat16_as_ushort(hi) << 16) |
           (uint32_t)__bfloat16_as_ushort(lo);
}

// ------------------------------------------------------------------
// Degree (by row, float -> dinv) + in-degree histogram (by col, int)
// ------------------------------------------------------------------
__global__ void k_count(const int* __restrict__ ei, int E) {
    for (int i = blockIdx.x * blockDim.x + threadIdx.x; i < E;
         i += gridDim.x * blockDim.x) {
        atomicAdd(&g_dinv[ei[i]], 1.0f);
        atomicAdd(&g_colcnt[ei[E + i]], 1);
    }
}

__global__ void k_dinv(int M) {
    int i = blockIdx.x * blockDim.x + threadIdx.x;
    if (i < M) g_dinv[i] = rsqrtf(g_dinv[i] + 1.0f);
}

// ---- 3-phase exclusive scan of colcnt -> colptr ----
__global__ void k_scan1(int M) {        // grid=NBLK, block=1024
    __shared__ int sm[1024];
    int tid = threadIdx.x;
    int i   = blockIdx.x * 1024 + tid;
    int v   = (i < M) ? g_colcnt[i] : 0;
    sm[tid] = v;
    __syncthreads();
    #pragma unroll
    for (int off = 1; off < 1024; off <<= 1) {
        int t = (tid >= off) ? sm[tid - off] : 0;
        __syncthreads();
        sm[tid] += t;
        __syncthreads();
    }
    if (i < M) g_colptr[i] = sm[tid] - v;   // block-local exclusive
    if (tid == 1023) g_blksum[blockIdx.x] = sm[1023];
}

// parallel scan of per-block sums
__global__ void k_scan2(int nb) {       // 1 block x 128 threads
    __shared__ int sm[128];
    int tid = threadIdx.x;
    int v = (tid < nb) ? g_blksum[tid] : 0;
    sm[tid] = v;
    __syncthreads();
    #pragma unroll
    for (int off = 1; off < 128; off <<= 1) {
        int t = (tid >= off) ? sm[tid - off] : 0;
        __syncthreads();
        sm[tid] += t;
        __syncthreads();
    }
    if (tid <= nb) g_blkoff[tid] = sm[tid] - v;   // exclusive
}

__global__ void k_scan3(int M, int E) {
    int i = blockIdx.x * blockDim.x + threadIdx.x;
    if (i < M) {
        int p = g_colptr[i] + g_blkoff[i >> 10];
        g_colptr[i] = p;
        g_cursor[i] = p;
    }
    if (i == 0) g_colptr[M] = E;
}

// ---- fill packed CSR records ----
__global__ void k_fill(const int* __restrict__ ei,
                       const float* __restrict__ ea, int E) {
    for (int i = blockIdx.x * blockDim.x + threadIdx.x; i < E;
         i += gridDim.x * blockDim.x) {
        int r = ei[i], c = ei[E + i];
        int pos = atomicAdd(&g_cursor[c], 1);
        int4 p;
        p.x = r;
        p.y = __float_as_int(ea[3 * i + 0]);
        p.z = __float_as_int(ea[3 * i + 1]);
        p.w = __float_as_int(ea[3 * i + 2]);
        g_epack[pos] = p;
    }
}

// ------------------------------------------------------------------
// Weight conversion: Wt[n][k] = split_bf16(W[k][n]) for 4 matrices
// ------------------------------------------------------------------
__global__ void k_wconv(const float* __restrict__ W0, const float* __restrict__ W1,
                        const float* __restrict__ W2, const float* __restrict__ W3) {
    int i = blockIdx.x * blockDim.x + threadIdx.x;
    if (i >= 4 * WTILE) return;
    int m = i >> 14, r = i & (WTILE - 1);
    int n = r >> 7, k = r & 127;
    const float* W = (m == 0) ? W0 : (m == 1) ? W1 : (m == 2) ? W2 : W3;
    float v = W[k * 128 + n];
    __nv_bfloat16 h = __float2bfloat16_rn(v);
    g_wbh[i] = h;
    g_wbl[i] = __float2bfloat16_rn(v - __bfloat162float(h));
}

// ------------------------------------------------------------------
// Tensor-core split-bf16 GEMM via mma.sync.m16n8k16:
//   C[M,128] = act(A)[M,128] @ W[128,128] + bias
//   act(A) = coeff ? relu(A)*mul+add : A   (fused BN)
//   C = (Ah + Al)@Bh + Ah@Bl  (fp32 accumulators, 2 passes sharing B)
// ------------------------------------------------------------------
__global__ __launch_bounds__(256, 1)
void k_gemm_mma(const float* __restrict__ A,
                const __nv_bfloat16* __restrict__ Bh,
                const __nv_bfloat16* __restrict__ Bl,
                const float* __restrict__ bias,
                const float* __restrict__ coeff,   // nullable [mul|add]
                float* __restrict__ C, int M)
{
    extern __shared__ char dsm[];
    char* pAh = dsm;
    char* pAl = dsm + ATILE;
    char* pBh = dsm + 2 * ATILE;
    char* pBl = dsm + 3 * ATILE;
    __shared__ float s_bias[128], s_mul[128], s_add[128];

    const int tid  = threadIdx.x;
    const int warp = tid >> 5;
    const int lane = tid & 31;
    const int g    = lane >> 2;
    const int tig  = lane & 3;
    const int m0   = blockIdx.x * 128;
    const bool useBN = (coeff != nullptr);

    if (tid < 128) {
        s_bias[tid] = bias[tid];
        if (useBN) { s_mul[tid] = coeff[tid]; s_add[tid] = coeff[128 + tid]; }
    }
    __syncthreads();   // s_mul/s_add read by all threads below

    #pragma unroll
    for (int it = 0; it < 8; it++) {
        int q = it * 256 + tid;
        int row = q >> 4, c8 = (q & 15) << 3;
        *(uint4*)(pBh + row * PITCH + c8 * 2) = *(const uint4*)(Bh + row * 128 + c8);
        *(uint4*)(pBl + row * PITCH + c8 * 2) = *(const uint4*)(Bl + row * 128 + c8);
    }

    #pragma unroll
    for (int it = 0; it < 16; it++) {
        int q = it * 256 + tid;
        int row = q >> 5, c4 = (q & 31) << 2;
        int grow = m0 + row;
        float4 v = make_float4(0.f, 0.f, 0.f, 0.f);
        if (grow < M) v = *(const float4*)(A + (size_t)grow * 128 + c4);
        float vv[4] = {v.x, v.y, v.z, v.w};
        if (useBN) {
            #pragma unroll
            for (int j = 0; j < 4; j++)
                vv[j] = fmaxf(vv[j], 0.f) * s_mul[c4 + j] + s_add[c4 + j];
        }
        __nv_bfloat16 h[4], l[4];
        #pragma unroll
        for (int j = 0; j < 4; j++) {
            h[j] = __float2bfloat16_rn(vv[j]);
            l[j] = __float2bfloat16_rn(vv[j] - __bfloat162float(h[j]));
        }
        uint2 hw, lw;
        hw.x = pack_bf2(h[0], h[1]); hw.y = pack_bf2(h[2], h[3]);
        lw.x = pack_bf2(l[0], l[1]); lw.y = pack_bf2(l[2], l[3]);
        *(uint2*)(pAh + row * PITCH + c4 * 2) = hw;
        *(uint2*)(pAl + row * PITCH + c4 * 2) = lw;
    }
    __syncthreads();

    float acc[16][4];
    #pragma unroll
    for (int nt = 0; nt < 16; nt++)
        #pragma unroll
        for (int j = 0; j < 4; j++) acc[nt][j] = 0.0f;

    const int arow = warp * 16;

    // ---- pass 1: (Ah + Al) @ Bh ----
    #pragma unroll
    for (int k8 = 0; k8 < 8; k8++) {
        uint32_t abase = (uint32_t)(arow + g) * PITCH + (uint32_t)k8 * 32 + 4u * tig;
        uint32_t ah[4], al[4];
        ah[0] = *(const uint32_t*)(pAh + abase);
        ah[1] = *(const uint32_t*)(pAh + abase + 8 * PITCH);
        ah[2] = *(const uint32_t*)(pAh + abase + 16);
        ah[3] = *(const uint32_t*)(pAh + abase + 8 * PITCH + 16);
        al[0] = *(const uint32_t*)(pAl + abase);
        al[1] = *(const uint32_t*)(pAl + abase + 8 * PITCH);
        al[2] = *(const uint32_t*)(pAl + abase + 16);
        al[3] = *(const uint32_t*)(pAl + abase + 8 * PITCH + 16);
        #pragma unroll
        for (int nt = 0; nt < 16; nt++) {
            uint32_t boff = (uint32_t)(nt * 8 + g) * PITCH + 4u * tig + k8 * 32;
            uint32_t b0 = *(const uint32_t*)(pBh + boff);
            uint32_t b1 = *(const uint32_t*)(pBh + boff + 16);
            asm volatile(
                "mma.sync.aligned.m16n8k16.row.col.f32.bf16.bf16.f32 "
                "{%0,%1,%2,%3}, {%4,%5,%6,%7}, {%8,%9}, {%0,%1,%2,%3};"
                : "+f"(acc[nt][0]), "+f"(acc[nt][1]),
                  "+f"(acc[nt][2]), "+f"(acc[nt][3])
                : "r"(ah[0]), "r"(ah[1]), "r"(ah[2]), "r"(ah[3]),
                  "r"(b0), "r"(b1));
            asm volatile(
                "mma.sync.aligned.m16n8k16.row.col.f32.bf16.bf16.f32 "
                "{%0,%1,%2,%3}, {%4,%5,%6,%7}, {%8,%9}, {%0,%1,%2,%3};"
                : "+f"(acc[nt][0]), "+f"(acc[nt][1]),
                  "+f"(acc[nt][2]), "+f"(acc[nt][3])
                : "r"(al[0]), "r"(al[1]), "r"(al[2]), "r"(al[3]),
                  "r"(b0), "r"(b1));
        }
    }
    // ---- pass 2: Ah @ Bl ----
    #pragma unroll
    for (int k8 = 0; k8 < 8; k8++) {
        uint32_t abase = (uint32_t)(arow + g) * PITCH + (uint32_t)k8 * 32 + 4u * tig;
        uint32_t ah[4];
        ah[0] = *(const uint32_t*)(pAh + abase);
        ah[1] = *(const uint32_t*)(pAh + abase + 8 * PITCH);
        ah[2] = *(const uint32_t*)(pAh + abase + 16);
        ah[3] = *(const uint32_t*)(pAh + abase + 8 * PITCH + 16);
        #pragma unroll
        for (int nt = 0; nt < 16; nt++) {
            uint32_t boff = (uint32_t)(nt * 8 + g) * PITCH + 4u * tig + k8 * 32;
            uint32_t b0 = *(const uint32_t*)(pBl + boff);
            uint32_t b1 = *(const uint32_t*)(pBl + boff + 16);
            asm volatile(
                "mma.sync.aligned.m16n8k16.row.col.f32.bf16.bf16.f32 "
                "{%0,%1,%2,%3}, {%4,%5,%6,%7}, {%8,%9}, {%0,%1,%2,%3};"
                : "+f"(acc[nt][0]), "+f"(acc[nt][1]),
                  "+f"(acc[nt][2]), "+f"(acc[nt][3])
                : "r"(ah[0]), "r"(ah[1]), "r"(ah[2]), "r"(ah[3]),
                  "r"(b0), "r"(b1));
        }
    }

    const int r0 = m0 + arow + g;
    const int r1 = r0 + 8;
    #pragma unroll
    for (int nt = 0; nt < 16; nt++) {
        int col = nt * 8 + tig * 2;
        float bx = s_bias[col], by = s_bias[col + 1];
        if (r0 < M) {
            float2 o = make_float2(acc[nt][0] + bx, acc[nt][1] + by);
            *(float2*)(C + (size_t)r0 * 128 + col) = o;
        }
        if (r1 < M) {
            float2 o = make_float2(acc[nt][2] + bx, acc[nt][3] + by);
            *(float2*)(C + (size_t)r1 * 128 + col) = o;
        }
    }
}

// ------------------------------------------------------------------
// CSR aggregation + fused BN statistics.  One warp per destination
// node (lane owns 4 feats).  4-edge unrolled inner loop: 4 epack + 4
// random h-row loads issued back-to-back (MLP~8) before any FMA, to
// saturate the L1tex/LTS queues instead of stalling at L2 latency.
// ------------------------------------------------------------------
__global__ __launch_bounds__(256)
void k_aggr(const float* __restrict__ h, const float* __restrict__ We,
            const float* __restrict__ be, int M)
{
    __shared__ double sm_s[128], sm_s2[128];
    const int tid  = threadIdx.x;
    const int lane = tid & 31;
    const int warp = (blockIdx.x * blockDim.x + tid) >> 5;
    const int nw   = (gridDim.x * blockDim.x) >> 5;
    const int f    = lane << 2;

    if (tid < 128) { sm_s[tid] = 0.0; sm_s2[tid] = 0.0; }
    __syncthreads();

    const float4 w0 = *(const float4*)(We + f);
    const float4 w1 = *(const float4*)(We + D + f);
    const float4 w2 = *(const float4*)(We + 2 * D + f);
    const float4 b4 = *(const float4*)(be + f);

    float ps[4]  = {0.f, 0.f, 0.f, 0.f};
    float ps2[4] = {0.f, 0.f, 0.f, 0.f};

    for (int n = warp; n < M; n += nw) {
        const int beg = g_colptr[n];
        const int end = g_colptr[n + 1];
        const float dcn = g_dinv[n];
        float4 acc = make_float4(0.f, 0.f, 0.f, 0.f);

        int pos = beg;
        // 4-edge unrolled: batch all loads first (8 independent mem ops)
        for (; pos + 4 <= end; pos += 4) {
            int4   ee[4];
            float4 hh[4];
            float  nr[4];
            #pragma unroll
            for (int u = 0; u < 4; u++) ee[u] = g_epack[pos + u];
            #pragma unroll
            for (int u = 0; u < 4; u++)
                hh[u] = *(const float4*)(h + (size_t)ee[u].x * D + f);
            #pragma unroll
            for (int u = 0; u < 4; u++) nr[u] = dcn * g_dinv[ee[u].x];
            #pragma unroll
            for (int u = 0; u < 4; u++) {
                float a0 = __int_as_float(ee[u].y);
                float a1 = __int_as_float(ee[u].z);
                float a2 = __int_as_float(ee[u].w);
                acc.x += fmaxf(hh[u].x + b4.x + a0*w0.x + a1*w1.x + a2*w2.x, 0.f) * nr[u];
                acc.y += fmaxf(hh[u].y + b4.y + a0*w0.y + a1*w1.y + a2*w2.y, 0.f) * nr[u];
                acc.z += fmaxf(hh[u].z + b4.z + a0*w0.z + a1*w1.z + a2*w2.z, 0.f) * nr[u];
                acc.w += fmaxf(hh[u].w + b4.w + a0*w0.w + a1*w1.w + a2*w2.w, 0.f) * nr[u];
            }
        }
        for (; pos < end; pos++) {
            int4 e0 = g_epack[pos];
            float nr0 = dcn * g_dinv[e0.x];
            float4 h0 = *(const float4*)(h + (size_t)e0.x * D + f);
            float a0 = __int_as_float(e0.y);
            float a1 = __int_as_float(e0.z);
            float a2 = __int_as_float(e0.w);
            acc.x += fmaxf(h0.x + b4.x + a0*w0.x + a1*w1.x + a2*w2.x, 0.f) * nr0;
            acc.y += fmaxf(h0.y + b4.y + a0*w0.y + a1*w1.y + a2*w2.y, 0.f) * nr0;
            acc.z += fmaxf(h0.z + b4.z + a0*w0.z + a1*w1.z + a2*w2.z, 0.f) * nr0;
            acc.w += fmaxf(h0.w + b4.w + a0*w0.w + a1*w1.w + a2*w2.w, 0.f) * nr0;
        }
        *(float4*)(g_acc + (size_t)n * D + f) = acc;

        // fused BN stats over relu(acc)
        float r0 = fmaxf(acc.x, 0.f), r1 = fmaxf(acc.y, 0.f);
        float r2 = fmaxf(acc.z, 0.f), r3 = fmaxf(acc.w, 0.f);
        ps[0] += r0; ps2[0] += r0 * r0;
        ps[1] += r1; ps2[1] += r1 * r1;
        ps[2] += r2; ps2[2] += r2 * r2;
        ps[3] += r3; ps2[3] += r3 * r3;
    }

    #pragma unroll
    for (int j = 0; j < 4; j++) {
        atomicAdd(&sm_s[f + j],  (double)ps[j]);
        atomicAdd(&sm_s2[f + j], (double)ps2[j]);
    }
    __syncthreads();
    if (tid < 128) {
        atomicAdd(&g_stats[tid],     sm_s[tid]);
        atomicAdd(&g_stats[D + tid], sm_s2[tid]);
    }
}

__global__ void k_bncoeff(const float* __restrict__ g,
                          const float* __restrict__ bt, int M) {
    const int f = threadIdx.x;
    double mean = g_stats[f] / (double)M;
    double var  = g_stats[D + f] / (double)M - mean * mean;
    float mul = g[f] * rsqrtf((float)var + 1e-5f);
    g_coeff[f]     = mul;
    g_coeff[D + f] = bt[f] - (float)mean * mul;
}

// ------------------------------------------------------------------
extern "C" void kernel_launch(void* const* d_in, const int* in_sizes, int n_in,
                              void* d_out, int out_size)
{
    const float* x  = (const float*)d_in[0];
    const int*   ei = (const int*)d_in[1];
    const float* ea = (const float*)d_in[2];
    const float* Wp[3]  = {(const float*)d_in[3],  (const float*)d_in[9],  (const float*)d_in[15]};
    const float* bp[3]  = {(const float*)d_in[4],  (const float*)d_in[10], (const float*)d_in[16]};
    const float* Wep[3] = {(const float*)d_in[5],  (const float*)d_in[11], (const float*)d_in[17]};
    const float* bep[3] = {(const float*)d_in[6],  (const float*)d_in[12], (const float*)d_in[18]};
    const float* gp[3]  = {(const float*)d_in[7],  (const float*)d_in[13], (const float*)d_in[19]};
    const float* btp[3] = {(const float*)d_in[8],  (const float*)d_in[14], (const float*)d_in[20]};
    const float* Wl = (const float*)d_in[21];
    const float* bl = (const float*)d_in[22];

    const int M = in_sizes[0] / D;
    const int E = in_sizes[1] / 2;

    // Resolve __device__ symbols via the runtime (GB300 ATS pitfall).
    void *p_h, *p_acc, *p_dinv, *p_stats, *p_coeff, *p_wbh, *p_wbl, *p_colcnt;
    cudaGetSymbolAddress(&p_h, g_h);
    cudaGetSymbolAddress(&p_acc, g_acc);
    cudaGetSymbolAddress(&p_dinv, g_dinv);
    cudaGetSymbolAddress(&p_stats, g_stats);
    cudaGetSymbolAddress(&p_coeff, g_coeff);
    cudaGetSymbolAddress(&p_wbh, g_wbh);
    cudaGetSymbolAddress(&p_wbl, g_wbl);
    cudaGetSymbolAddress(&p_colcnt, g_colcnt);
    const __nv_bfloat16* wbh = (const __nv_bfloat16*)p_wbh;
    const __nv_bfloat16* wbl = (const __nv_bfloat16*)p_wbl;

    cudaFuncSetAttribute(k_gemm_mma, cudaFuncAttributeMaxDynamicSharedMemorySize,
                         DYNSMEM);

    // weight split (once per launch)
    k_wconv<<<(4 * WTILE + 255) / 256, 256>>>(Wp[0], Wp[1], Wp[2], Wl);

    // degrees + CSR build (once per launch, reused for all 3 layers)
    cudaMemsetAsync(p_dinv, 0, (size_t)M * sizeof(float));
    cudaMemsetAsync(p_colcnt, 0, (size_t)M * sizeof(int));
    k_count<<<2048, 256>>>(ei, E);
    k_dinv<<<(M + 255) / 256, 256>>>(M);
    const int nb = (M + 1023) / 1024;
    k_scan1<<<nb, 1024>>>(M);
    k_scan2<<<1, 128>>>(nb);
    k_scan3<<<(M + 255) / 256, 256>>>(M, E);
    k_fill<<<2048, 256>>>(ei, ea, E);

    const int gemm_grid = (M + 127) / 128;
    const float* in = x;
    const float* cf = nullptr;
    for (int L = 0; L < 3; L++) {
        k_gemm_mma<<<gemm_grid, 256, DYNSMEM>>>(in, wbh + L * WTILE,
                                                wbl + L * WTILE,
                                                bp[L], cf, (float*)p_h, M);
        cudaMemsetAsync(p_stats, 0, 2 * D * sizeof(double));
        k_aggr<<<2048, 256>>>((const float*)p_h, Wep[L], bep[L], M);
        k_bncoeff<<<1, 128>>>(gp[L], btp[L], M);
        in = (const float*)p_acc;
        cf = (const float*)p_coeff;
    }
    k_gemm_mma<<<gemm_grid, 256, DYNSMEM>>>(in, wbh + 3 * WTILE, wbl + 3 * WTILE,
                                            bl, cf, (float*)d_out, M);
}

// round 12
// speedup vs baseline: 1.9023x; 1.0212x over previous
#include <cuda_runtime.h>
#include <cuda_bf16.h>
#include <cstdint>

#define D 128
#define NMAX 100000
#define EMAX 1600000
#define NBLK 98                         // ceil(NMAX/1024)
#define WTILE (128 * 128)
#define PITCH 272                       // smem row pitch in bytes (136 bf16)
#define ATILE (128 * PITCH)             // 34816 B per 128x128 bf16 tile
#define DYNSMEM (4 * ATILE)             // Ah, Al, Bh, Bl = 139264 B
#define BN_EPS 1e-5f

// ---- scratch (static device globals; no allocation allowed) ----
__device__ float  g_h[(size_t)NMAX * D];     // GEMM out / edge gather src
__device__ float  g_acc[(size_t)NMAX * D];   // aggregation output
__device__ float  g_dinv[NMAX];              // deg^-0.5
__device__ double g_stats[2 * D];            // per-feature sum, sumsq
__device__ __align__(16) __nv_bfloat16 g_wbh[4 * WTILE];  // W^T hi (bf16)
__device__ __align__(16) __nv_bfloat16 g_wbl[4 * WTILE];  // W^T lo residual
// CSR-by-destination structures
__device__ int    g_colcnt[NMAX];
__device__ int    g_colptr[NMAX + 1];
__device__ int    g_cursor[NMAX];
__device__ int    g_blksum[NBLK + 1];
__device__ int    g_blkoff[NBLK + 1];
__device__ __align__(16) int4 g_epack[EMAX]; // {row, bits(a0), bits(a1), bits(a2)}
__device__ float  g_enrm[EMAX];              // dinv[row]*dinv[col], edge order

__device__ __forceinline__ uint32_t pack_bf2(__nv_bfloat16 lo, __nv_bfloat16 hi) {
    return ((uint32_t)__bfloat16_as_ushort(hi) << 16) |
           (uint32_t)__bfloat16_as_ushort(lo);
}

// ------------------------------------------------------------------
// Degree (by row, float -> dinv) + in-degree histogram (by col, int)
// ------------------------------------------------------------------
__global__ void k_count(const int* __restrict__ ei, int E) {
    for (int i = blockIdx.x * blockDim.x + threadIdx.x; i < E;
         i += gridDim.x * blockDim.x) {
        atomicAdd(&g_dinv[ei[i]], 1.0f);
        atomicAdd(&g_colcnt[ei[E + i]], 1);
    }
}

__global__ void k_dinv(int M) {
    int i = blockIdx.x * blockDim.x + threadIdx.x;
    if (i < M) g_dinv[i] = rsqrtf(g_dinv[i] + 1.0f);
}

// ---- 3-phase exclusive scan of colcnt -> colptr ----
__global__ void k_scan1(int M) {        // grid=NBLK, block=1024
    __shared__ int sm[1024];
    int tid = threadIdx.x;
    int i   = blockIdx.x * 1024 + tid;
    int v   = (i < M) ? g_colcnt[i] : 0;
    sm[tid] = v;
    __syncthreads();
    #pragma unroll
    for (int off = 1; off < 1024; off <<= 1) {
        int t = (tid >= off) ? sm[tid - off] : 0;
        __syncthreads();
        sm[tid] += t;
        __syncthreads();
    }
    if (i < M) g_colptr[i] = sm[tid] - v;   // block-local exclusive
    if (tid == 1023) g_blksum[blockIdx.x] = sm[1023];
}

__global__ void k_scan2(int nb) {       // 1 block x 128 threads
    __shared__ int sm[128];
    int tid = threadIdx.x;
    int v = (tid < nb) ? g_blksum[tid] : 0;
    sm[tid] = v;
    __syncthreads();
    #pragma unroll
    for (int off = 1; off < 128; off <<= 1) {
        int t = (tid >= off) ? sm[tid - off] : 0;
        __syncthreads();
        sm[tid] += t;
        __syncthreads();
    }
    if (tid <= nb) g_blkoff[tid] = sm[tid] - v;   // exclusive
}

__global__ void k_scan3(int M, int E) {
    int i = blockIdx.x * blockDim.x + threadIdx.x;
    if (i < M) {
        int p = g_colptr[i] + g_blkoff[i >> 10];
        g_colptr[i] = p;
        g_cursor[i] = p;
    }
    if (i == 0) g_colptr[M] = E;
}

// ---- fill packed CSR records + precomputed per-edge norm ----
__global__ void k_fill(const int* __restrict__ ei,
                       const float* __restrict__ ea, int E) {
    for (int i = blockIdx.x * blockDim.x + threadIdx.x; i < E;
         i += gridDim.x * blockDim.x) {
        int r = ei[i], c = ei[E + i];
        int pos = atomicAdd(&g_cursor[c], 1);
        int4 p;
        p.x = r;
        p.y = __float_as_int(ea[3 * i + 0]);
        p.z = __float_as_int(ea[3 * i + 1]);
        p.w = __float_as_int(ea[3 * i + 2]);
        g_epack[pos] = p;
        g_enrm[pos]  = g_dinv[r] * g_dinv[c];
    }
}

// ------------------------------------------------------------------
// Weight conversion: Wt[n][k] = split_bf16(W[k][n]) for 4 matrices
// ------------------------------------------------------------------
__global__ void k_wconv(const float* __restrict__ W0, const float* __restrict__ W1,
                        const float* __restrict__ W2, const float* __restrict__ W3) {
    int i = blockIdx.x * blockDim.x + threadIdx.x;
    if (i >= 4 * WTILE) return;
    int m = i >> 14, r = i & (WTILE - 1);
    int n = r >> 7, k = r & 127;
    const float* W = (m == 0) ? W0 : (m == 1) ? W1 : (m == 2) ? W2 : W3;
    float v = W[k * 128 + n];
    __nv_bfloat16 h = __float2bfloat16_rn(v);
    g_wbh[i] = h;
    g_wbl[i] = __float2bfloat16_rn(v - __bfloat162float(h));
}

// ------------------------------------------------------------------
// Tensor-core split-bf16 GEMM via mma.sync.m16n8k16:
//   C[M,128] = act(A)[M,128] @ W[128,128] + bias
//   act(A) = useBN ? relu(A)*mul+add : A
//   BN coeffs computed IN-CTA from g_stats (kills k_bncoeff launches).
//   C = (Ah + Al)@Bh + Ah@Bl  (fp32 accumulators, 2 passes sharing B)
// ------------------------------------------------------------------
__global__ __launch_bounds__(256, 1)
void k_gemm_mma(const float* __restrict__ A,
                const __nv_bfloat16* __restrict__ Bh,
                const __nv_bfloat16* __restrict__ Bl,
                const float* __restrict__ bias,
                const float* __restrict__ gam,   // nullable -> no BN
                const float* __restrict__ bet,
                float* __restrict__ C, int M)
{
    extern __shared__ char dsm[];
    char* pAh = dsm;
    char* pAl = dsm + ATILE;
    char* pBh = dsm + 2 * ATILE;
    char* pBl = dsm + 3 * ATILE;
    __shared__ float s_bias[128], s_mul[128], s_add[128];

    const int tid  = threadIdx.x;
    const int warp = tid >> 5;
    const int lane = tid & 31;
    const int g    = lane >> 2;
    const int tig  = lane & 3;
    const int m0   = blockIdx.x * 128;
    const bool useBN = (gam != nullptr);

    if (tid < 128) {
        s_bias[tid] = bias[tid];
        if (useBN) {
            double mean = g_stats[tid] / (double)M;
            double var  = g_stats[D + tid] / (double)M - mean * mean;
            float mul = gam[tid] * rsqrtf((float)var + BN_EPS);
            s_mul[tid] = mul;
            s_add[tid] = bet[tid] - (float)mean * mul;
        }
    }
    __syncthreads();   // s_mul/s_add read by all threads below

    #pragma unroll
    for (int it = 0; it < 8; it++) {
        int q = it * 256 + tid;
        int row = q >> 4, c8 = (q & 15) << 3;
        *(uint4*)(pBh + row * PITCH + c8 * 2) = *(const uint4*)(Bh + row * 128 + c8);
        *(uint4*)(pBl + row * PITCH + c8 * 2) = *(const uint4*)(Bl + row * 128 + c8);
    }

    #pragma unroll
    for (int it = 0; it < 16; it++) {
        int q = it * 256 + tid;
        int row = q >> 5, c4 = (q & 31) << 2;
        int grow = m0 + row;
        float4 v = make_float4(0.f, 0.f, 0.f, 0.f);
        if (grow < M) v = *(const float4*)(A + (size_t)grow * 128 + c4);
        float vv[4] = {v.x, v.y, v.z, v.w};
        if (useBN) {
            #pragma unroll
            for (int j = 0; j < 4; j++)
                vv[j] = fmaxf(vv[j], 0.f) * s_mul[c4 + j] + s_add[c4 + j];
        }
        __nv_bfloat16 h[4], l[4];
        #pragma unroll
        for (int j = 0; j < 4; j++) {
            h[j] = __float2bfloat16_rn(vv[j]);
            l[j] = __float2bfloat16_rn(vv[j] - __bfloat162float(h[j]));
        }
        uint2 hw, lw;
        hw.x = pack_bf2(h[0], h[1]); hw.y = pack_bf2(h[2], h[3]);
        lw.x = pack_bf2(l[0], l[1]); lw.y = pack_bf2(l[2], l[3]);
        *(uint2*)(pAh + row * PITCH + c4 * 2) = hw;
        *(uint2*)(pAl + row * PITCH + c4 * 2) = lw;
    }
    __syncthreads();

    float acc[16][4];
    #pragma unroll
    for (int nt = 0; nt < 16; nt++)
        #pragma unroll
        for (int j = 0; j < 4; j++) acc[nt][j] = 0.0f;

    const int arow = warp * 16;

    // ---- pass 1: (Ah + Al) @ Bh ----
    #pragma unroll
    for (int k8 = 0; k8 < 8; k8++) {
        uint32_t abase = (uint32_t)(arow + g) * PITCH + (uint32_t)k8 * 32 + 4u * tig;
        uint32_t ah[4], al[4];
        ah[0] = *(const uint32_t*)(pAh + abase);
        ah[1] = *(const uint32_t*)(pAh + abase + 8 * PITCH);
        ah[2] = *(const uint32_t*)(pAh + abase + 16);
        ah[3] = *(const uint32_t*)(pAh + abase + 8 * PITCH + 16);
        al[0] = *(const uint32_t*)(pAl + abase);
        al[1] = *(const uint32_t*)(pAl + abase + 8 * PITCH);
        al[2] = *(const uint32_t*)(pAl + abase + 16);
        al[3] = *(const uint32_t*)(pAl + abase + 8 * PITCH + 16);
        #pragma unroll
        for (int nt = 0; nt < 16; nt++) {
            uint32_t boff = (uint32_t)(nt * 8 + g) * PITCH + 4u * tig + k8 * 32;
            uint32_t b0 = *(const uint32_t*)(pBh + boff);
            uint32_t b1 = *(const uint32_t*)(pBh + boff + 16);
            asm volatile(
                "mma.sync.aligned.m16n8k16.row.col.f32.bf16.bf16.f32 "
                "{%0,%1,%2,%3}, {%4,%5,%6,%7}, {%8,%9}, {%0,%1,%2,%3};"
                : "+f"(acc[nt][0]), "+f"(acc[nt][1]),
                  "+f"(acc[nt][2]), "+f"(acc[nt][3])
                : "r"(ah[0]), "r"(ah[1]), "r"(ah[2]), "r"(ah[3]),
                  "r"(b0), "r"(b1));
            asm volatile(
                "mma.sync.aligned.m16n8k16.row.col.f32.bf16.bf16.f32 "
                "{%0,%1,%2,%3}, {%4,%5,%6,%7}, {%8,%9}, {%0,%1,%2,%3};"
                : "+f"(acc[nt][0]), "+f"(acc[nt][1]),
                  "+f"(acc[nt][2]), "+f"(acc[nt][3])
                : "r"(al[0]), "r"(al[1]), "r"(al[2]), "r"(al[3]),
                  "r"(b0), "r"(b1));
        }
    }
    // ---- pass 2: Ah @ Bl ----
    #pragma unroll
    for (int k8 = 0; k8 < 8; k8++) {
        uint32_t abase = (uint32_t)(arow + g) * PITCH + (uint32_t)k8 * 32 + 4u * tig;
        uint32_t ah[4];
        ah[0] = *(const uint32_t*)(pAh + abase);
        ah[1] = *(const uint32_t*)(pAh + abase + 8 * PITCH);
        ah[2] = *(const uint32_t*)(pAh + abase + 16);
        ah[3] = *(const uint32_t*)(pAh + abase + 8 * PITCH + 16);
        #pragma unroll
        for (int nt = 0; nt < 16; nt++) {
            uint32_t boff = (uint32_t)(nt * 8 + g) * PITCH + 4u * tig + k8 * 32;
            uint32_t b0 = *(const uint32_t*)(pBl + boff);
            uint32_t b1 = *(const uint32_t*)(pBl + boff + 16);
            asm volatile(
                "mma.sync.aligned.m16n8k16.row.col.f32.bf16.bf16.f32 "
                "{%0,%1,%2,%3}, {%4,%5,%6,%7}, {%8,%9}, {%0,%1,%2,%3};"
                : "+f"(acc[nt][0]), "+f"(acc[nt][1]),
                  "+f"(acc[nt][2]), "+f"(acc[nt][3])
                : "r"(ah[0]), "r"(ah[1]), "r"(ah[2]), "r"(ah[3]),
                  "r"(b0), "r"(b1));
        }
    }

    const int r0 = m0 + arow + g;
    const int r1 = r0 + 8;
    #pragma unroll
    for (int nt = 0; nt < 16; nt++) {
        int col = nt * 8 + tig * 2;
        float bx = s_bias[col], by = s_bias[col + 1];
        if (r0 < M) {
            float2 o = make_float2(acc[nt][0] + bx, acc[nt][1] + by);
            *(float2*)(C + (size_t)r0 * 128 + col) = o;
        }
        if (r1 < M) {
            float2 o = make_float2(acc[nt][2] + bx, acc[nt][3] + by);
            *(float2*)(C + (size_t)r1 * 128 + col) = o;
        }
    }
}

// ------------------------------------------------------------------
// CSR aggregation + fused BN statistics.  One warp per destination
// node (lane owns 4 feats).  4-edge unroll; per-edge norm comes from
// the contiguous g_enrm array (L1-hit) instead of a random dinv load
// -> only ONE dependent random load (the h row) per edge.
// ------------------------------------------------------------------
__global__ __launch_bounds__(256)
void k_aggr(const float* __restrict__ h, const float* __restrict__ We,
            const float* __restrict__ be, int M)
{
    __shared__ double sm_s[128], sm_s2[128];
    const int tid  = threadIdx.x;
    const int lane = tid & 31;
    const int warp = (blockIdx.x * blockDim.x + tid) >> 5;
    const int nw   = (gridDim.x * blockDim.x) >> 5;
    const int f    = lane << 2;

    if (tid < 128) { sm_s[tid] = 0.0; sm_s2[tid] = 0.0; }
    __syncthreads();

    const float4 w0 = *(const float4*)(We + f);
    const float4 w1 = *(const float4*)(We + D + f);
    const float4 w2 = *(const float4*)(We + 2 * D + f);
    const float4 b4 = *(const float4*)(be + f);

    float ps[4]  = {0.f, 0.f, 0.f, 0.f};
    float ps2[4] = {0.f, 0.f, 0.f, 0.f};

    for (int n = warp; n < M; n += nw) {
        const int beg = g_colptr[n];
        const int end = g_colptr[n + 1];
        float4 acc = make_float4(0.f, 0.f, 0.f, 0.f);

        int pos = beg;
        for (; pos + 4 <= end; pos += 4) {
            int4   ee[4];
            float4 hh[4];
            float  nr[4];
            #pragma unroll
            for (int u = 0; u < 4; u++) ee[u] = g_epack[pos + u];
            #pragma unroll
            for (int u = 0; u < 4; u++) nr[u] = g_enrm[pos + u];
            #pragma unroll
            for (int u = 0; u < 4; u++)
                hh[u] = *(const float4*)(h + (size_t)ee[u].x * D + f);
            #pragma unroll
            for (int u = 0; u < 4; u++) {
                float a0 = __int_as_float(ee[u].y);
                float a1 = __int_as_float(ee[u].z);
                float a2 = __int_as_float(ee[u].w);
                acc.x += fmaxf(hh[u].x + b4.x + a0*w0.x + a1*w1.x + a2*w2.x, 0.f) * nr[u];
                acc.y += fmaxf(hh[u].y + b4.y + a0*w0.y + a1*w1.y + a2*w2.y, 0.f) * nr[u];
                acc.z += fmaxf(hh[u].z + b4.z + a0*w0.z + a1*w1.z + a2*w2.z, 0.f) * nr[u];
                acc.w += fmaxf(hh[u].w + b4.w + a0*w0.w + a1*w1.w + a2*w2.w, 0.f) * nr[u];
            }
        }
        for (; pos < end; pos++) {
            int4 e0 = g_epack[pos];
            float nr0 = g_enrm[pos];
            float4 h0 = *(const float4*)(h + (size_t)e0.x * D + f);
            float a0 = __int_as_float(e0.y);
            float a1 = __int_as_float(e0.z);
            float a2 = __int_as_float(e0.w);
            acc.x += fmaxf(h0.x + b4.x + a0*w0.x + a1*w1.x + a2*w2.x, 0.f) * nr0;
            acc.y += fmaxf(h0.y + b4.y + a0*w0.y + a1*w1.y + a2*w2.y, 0.f) * nr0;
            acc.z += fmaxf(h0.z + b4.z + a0*w0.z + a1*w1.z + a2*w2.z, 0.f) * nr0;
            acc.w += fmaxf(h0.w + b4.w + a0*w0.w + a1*w1.w + a2*w2.w, 0.f) * nr0;
        }
        *(float4*)(g_acc + (size_t)n * D + f) = acc;

        // fused BN stats over relu(acc)
        float r0 = fmaxf(acc.x, 0.f), r1 = fmaxf(acc.y, 0.f);
        float r2 = fmaxf(acc.z, 0.f), r3 = fmaxf(acc.w, 0.f);
        ps[0] += r0; ps2[0] += r0 * r0;
        ps[1] += r1; ps2[1] += r1 * r1;
        ps[2] += r2; ps2[2] += r2 * r2;
        ps[3] += r3; ps2[3] += r3 * r3;
    }

    #pragma unroll
    for (int j = 0; j < 4; j++) {
        atomicAdd(&sm_s[f + j],  (double)ps[j]);
        atomicAdd(&sm_s2[f + j], (double)ps2[j]);
    }
    __syncthreads();
    if (tid < 128) {
        atomicAdd(&g_stats[tid],     sm_s[tid]);
        atomicAdd(&g_stats[D + tid], sm_s2[tid]);
    }
}

// ------------------------------------------------------------------
extern "C" void kernel_launch(void* const* d_in, const int* in_sizes, int n_in,
                              void* d_out, int out_size)
{
    const float* x  = (const float*)d_in[0];
    const int*   ei = (const int*)d_in[1];
    const float* ea = (const float*)d_in[2];
    const float* Wp[3]  = {(const float*)d_in[3],  (const float*)d_in[9],  (const float*)d_in[15]};
    const float* bp[3]  = {(const float*)d_in[4],  (const float*)d_in[10], (const float*)d_in[16]};
    const float* Wep[3] = {(const float*)d_in[5],  (const float*)d_in[11], (const float*)d_in[17]};
    const float* bep[3] = {(const float*)d_in[6],  (const float*)d_in[12], (const float*)d_in[18]};
    const float* gp[3]  = {(const float*)d_in[7],  (const float*)d_in[13], (const float*)d_in[19]};
    const float* btp[3] = {(const float*)d_in[8],  (const float*)d_in[14], (const float*)d_in[20]};
    const float* Wl = (const float*)d_in[21];
    const float* bl = (const float*)d_in[22];

    const int M = in_sizes[0] / D;
    const int E = in_sizes[1] / 2;

    // Resolve __device__ symbols via the runtime (GB300 ATS pitfall).
    void *p_h, *p_acc, *p_dinv, *p_stats, *p_wbh, *p_wbl, *p_colcnt;
    cudaGetSymbolAddress(&p_h, g_h);
    cudaGetSymbolAddress(&p_acc, g_acc);
    cudaGetSymbolAddress(&p_dinv, g_dinv);
    cudaGetSymbolAddress(&p_stats, g_stats);
    cudaGetSymbolAddress(&p_wbh, g_wbh);
    cudaGetSymbolAddress(&p_wbl, g_wbl);
    cudaGetSymbolAddress(&p_colcnt, g_colcnt);
    const __nv_bfloat16* wbh = (const __nv_bfloat16*)p_wbh;
    const __nv_bfloat16* wbl = (const __nv_bfloat16*)p_wbl;

    cudaFuncSetAttribute(k_gemm_mma, cudaFuncAttributeMaxDynamicSharedMemorySize,
                         DYNSMEM);

    // secondary stream + fork/join events (created once; graph-capturable)
    static cudaStream_t s2 = nullptr;
    static cudaEvent_t evA = nullptr, evB = nullptr;
    if (!s2) {
        cudaStreamCreate(&s2);
        cudaEventCreateWithFlags(&evA, cudaEventDisableTiming);
        cudaEventCreateWithFlags(&evB, cudaEventDisableTiming);
    }

    // ---- fork: CSR/degree build on s2, wconv+gemm1 on main stream ----
    cudaEventRecord(evA, 0);
    cudaStreamWaitEvent(s2, evA, 0);

    cudaMemsetAsync(p_dinv, 0, (size_t)M * sizeof(float), s2);
    cudaMemsetAsync(p_colcnt, 0, (size_t)M * sizeof(int), s2);
    k_count<<<2048, 256, 0, s2>>>(ei, E);
    k_dinv<<<(M + 255) / 256, 256, 0, s2>>>(M);
    const int nb = (M + 1023) / 1024;
    k_scan1<<<nb, 1024, 0, s2>>>(M);
    k_scan2<<<1, 128, 0, s2>>>(nb);
    k_scan3<<<(M + 255) / 256, 256, 0, s2>>>(M, E);
    k_fill<<<2048, 256, 0, s2>>>(ei, ea, E);
    cudaEventRecord(evB, s2);

    const int gemm_grid = (M + 127) / 128;
    k_wconv<<<(4 * WTILE + 255) / 256, 256>>>(Wp[0], Wp[1], Wp[2], Wl);
    // layer-1 GEMM (no BN) overlaps the CSR build
    k_gemm_mma<<<gemm_grid, 256, DYNSMEM>>>(x, wbh, wbl, bp[0],
                                            nullptr, nullptr, (float*)p_h, M);
    // join: aggregation needs both gemm1 (main) and CSR (s2)
    cudaStreamWaitEvent(0, evB, 0);

    for (int L = 0; L < 3; L++) {
        if (L > 0)
            k_gemm_mma<<<gemm_grid, 256, DYNSMEM>>>((const float*)p_acc,
                                                    wbh + L * WTILE,
                                                    wbl + L * WTILE, bp[L],
                                                    gp[L - 1], btp[L - 1],
                                                    (float*)p_h, M);
        cudaMemsetAsync(p_stats, 0, 2 * D * sizeof(double));
        k_aggr<<<2048, 256>>>((const float*)p_h, Wep[L], bep[L], M);
    }
    k_gemm_mma<<<gemm_grid, 256, DYNSMEM>>>((const float*)p_acc,
                                            wbh + 3 * WTILE, wbl + 3 * WTILE,
                                            bl, gp[2], btp[2], (float*)d_out, M);
}

// round 13
// speedup vs baseline: 2.0047x; 1.0538x over previous
#include <cuda_runtime.h>
#include <cuda_bf16.h>
#include <cstdint>

#define D 128
#define NMAX 100000
#define EMAX 1600000
#define NBLK 98                         // ceil(NMAX/1024)
#define WTILE (128 * 128)
#define PITCH 272                       // smem row pitch in bytes (136 bf16)
#define ATILE (128 * PITCH)             // 34816 B per 128x128 bf16 tile
#define DYNSMEM (4 * ATILE)             // Ah, Al, Bh, Bl = 139264 B
#define BN_EPS 1e-5f

// ---- scratch (static device globals; no allocation allowed) ----
__device__ float  g_h[(size_t)NMAX * D];     // GEMM out / edge gather src
__device__ float  g_acc[(size_t)NMAX * D];   // aggregation output
__device__ float  g_dinv[NMAX];              // deg^-0.5
__device__ double g_stats4[4][2 * D];        // per-layer BN sum/sumsq
__device__ __align__(16) __nv_bfloat16 g_wbh[4 * WTILE];  // W^T hi (bf16)
__device__ __align__(16) __nv_bfloat16 g_wbl[4 * WTILE];  // W^T lo residual
// CSR-by-destination structures
__device__ int    g_colcnt[NMAX];
__device__ int    g_colptr[NMAX + 1];
__device__ int    g_cursor[NMAX];
__device__ int    g_blksum[NBLK + 1];
__device__ int    g_blkoff[NBLK + 1];
__device__ __align__(16) int4 g_epack[EMAX]; // {row, bits(a0), bits(a1), bits(a2)}
__device__ float  g_enrm[EMAX];              // dinv[row]*dinv[col], edge order

__device__ __forceinline__ uint32_t pack_bf2(__nv_bfloat16 lo, __nv_bfloat16 hi) {
    return ((uint32_t)__bfloat16_as_ushort(hi) << 16) |
           (uint32_t)__bfloat16_as_ushort(lo);
}

// ------------------------------------------------------------------
// Degree (by row, float -> dinv) + in-degree histogram (by col, int)
// ------------------------------------------------------------------
__global__ void k_count(const int* __restrict__ ei, int E) {
    for (int i = blockIdx.x * blockDim.x + threadIdx.x; i < E;
         i += gridDim.x * blockDim.x) {
        atomicAdd(&g_dinv[ei[i]], 1.0f);
        atomicAdd(&g_colcnt[ei[E + i]], 1);
    }
}

__global__ void k_dinv(int M) {
    int i = blockIdx.x * blockDim.x + threadIdx.x;
    if (i < M) g_dinv[i] = rsqrtf(g_dinv[i] + 1.0f);
}

// ---- 3-phase exclusive scan of colcnt -> colptr ----
__global__ void k_scan1(int M) {        // grid=NBLK, block=1024
    __shared__ int sm[1024];
    int tid = threadIdx.x;
    int i   = blockIdx.x * 1024 + tid;
    int v   = (i < M) ? g_colcnt[i] : 0;
    sm[tid] = v;
    __syncthreads();
    #pragma unroll
    for (int off = 1; off < 1024; off <<= 1) {
        int t = (tid >= off) ? sm[tid - off] : 0;
        __syncthreads();
        sm[tid] += t;
        __syncthreads();
    }
    if (i < M) g_colptr[i] = sm[tid] - v;   // block-local exclusive
    if (tid == 1023) g_blksum[blockIdx.x] = sm[1023];
}

__global__ void k_scan2(int nb) {       // 1 block x 128 threads
    __shared__ int sm[128];
    int tid = threadIdx.x;
    int v = (tid < nb) ? g_blksum[tid] : 0;
    sm[tid] = v;
    __syncthreads();
    #pragma unroll
    for (int off = 1; off < 128; off <<= 1) {
        int t = (tid >= off) ? sm[tid - off] : 0;
        __syncthreads();
        sm[tid] += t;
        __syncthreads();
    }
    if (tid <= nb) g_blkoff[tid] = sm[tid] - v;   // exclusive
}

__global__ void k_scan3(int M, int E) {
    int i = blockIdx.x * blockDim.x + threadIdx.x;
    if (i < M) {
        int p = g_colptr[i] + g_blkoff[i >> 10];
        g_colptr[i] = p;
        g_cursor[i] = p;
    }
    if (i == 0) g_colptr[M] = E;
}

// ---- fill packed CSR records + precomputed per-edge norm ----
__global__ void k_fill(const int* __restrict__ ei,
                       const float* __restrict__ ea, int E) {
    for (int i = blockIdx.x * blockDim.x + threadIdx.x; i < E;
         i += gridDim.x * blockDim.x) {
        int r = ei[i], c = ei[E + i];
        int pos = atomicAdd(&g_cursor[c], 1);
        int4 p;
        p.x = r;
        p.y = __float_as_int(ea[3 * i + 0]);
        p.z = __float_as_int(ea[3 * i + 1]);
        p.w = __float_as_int(ea[3 * i + 2]);
        g_epack[pos] = p;
        g_enrm[pos]  = g_dinv[r] * g_dinv[c];
    }
}

// ------------------------------------------------------------------
// Weight conversion: Wt[n][k] = split_bf16(W[k][n]) for 4 matrices
// ------------------------------------------------------------------
__global__ void k_wconv(const float* __restrict__ W0, const float* __restrict__ W1,
                        const float* __restrict__ W2, const float* __restrict__ W3) {
    int i = blockIdx.x * blockDim.x + threadIdx.x;
    if (i >= 4 * WTILE) return;
    int m = i >> 14, r = i & (WTILE - 1);
    int n = r >> 7, k = r & 127;
    const float* W = (m == 0) ? W0 : (m == 1) ? W1 : (m == 2) ? W2 : W3;
    float v = W[k * 128 + n];
    __nv_bfloat16 h = __float2bfloat16_rn(v);
    g_wbh[i] = h;
    g_wbl[i] = __float2bfloat16_rn(v - __bfloat162float(h));
}

// ------------------------------------------------------------------
// Tensor-core split-bf16 GEMM via mma.sync.m16n8k16:
//   C[M,128] = act(A)[M,128] @ W[128,128] + bias
//   act(A) = stats ? relu(A)*mul+add : A  (BN coeffs from stats in-CTA)
//   C = (Ah + Al)@Bh + Ah@Bl  (fp32 accumulators, 2 passes sharing B)
// ------------------------------------------------------------------
__global__ __launch_bounds__(256, 1)
void k_gemm_mma(const float* __restrict__ A,
                const __nv_bfloat16* __restrict__ Bh,
                const __nv_bfloat16* __restrict__ Bl,
                const float* __restrict__ bias,
                const float* __restrict__ gam,   // nullable -> no BN
                const float* __restrict__ bet,
                const double* __restrict__ stats,
                float* __restrict__ C, int M)
{
    extern __shared__ char dsm[];
    char* pAh = dsm;
    char* pAl = dsm + ATILE;
    char* pBh = dsm + 2 * ATILE;
    char* pBl = dsm + 3 * ATILE;
    __shared__ float s_bias[128], s_mul[128], s_add[128];

    const int tid  = threadIdx.x;
    const int warp = tid >> 5;
    const int lane = tid & 31;
    const int g    = lane >> 2;
    const int tig  = lane & 3;
    const int m0   = blockIdx.x * 128;
    const bool useBN = (gam != nullptr);

    if (tid < 128) {
        s_bias[tid] = bias[tid];
        if (useBN) {
            double mean = stats[tid] / (double)M;
            double var  = stats[D + tid] / (double)M - mean * mean;
            float mul = gam[tid] * rsqrtf((float)var + BN_EPS);
            s_mul[tid] = mul;
            s_add[tid] = bet[tid] - (float)mean * mul;
        }
    }
    __syncthreads();   // s_mul/s_add read by all threads below

    #pragma unroll
    for (int it = 0; it < 8; it++) {
        int q = it * 256 + tid;
        int row = q >> 4, c8 = (q & 15) << 3;
        *(uint4*)(pBh + row * PITCH + c8 * 2) = *(const uint4*)(Bh + row * 128 + c8);
        *(uint4*)(pBl + row * PITCH + c8 * 2) = *(const uint4*)(Bl + row * 128 + c8);
    }

    #pragma unroll
    for (int it = 0; it < 16; it++) {
        int q = it * 256 + tid;
        int row = q >> 5, c4 = (q & 31) << 2;
        int grow = m0 + row;
        float4 v = make_float4(0.f, 0.f, 0.f, 0.f);
        if (grow < M) v = *(const float4*)(A + (size_t)grow * 128 + c4);
        float vv[4] = {v.x, v.y, v.z, v.w};
        if (useBN) {
            #pragma unroll
            for (int j = 0; j < 4; j++)
                vv[j] = fmaxf(vv[j], 0.f) * s_mul[c4 + j] + s_add[c4 + j];
        }
        __nv_bfloat16 h[4], l[4];
        #pragma unroll
        for (int j = 0; j < 4; j++) {
            h[j] = __float2bfloat16_rn(vv[j]);
            l[j] = __float2bfloat16_rn(vv[j] - __bfloat162float(h[j]));
        }
        uint2 hw, lw;
        hw.x = pack_bf2(h[0], h[1]); hw.y = pack_bf2(h[2], h[3]);
        lw.x = pack_bf2(l[0], l[1]); lw.y = pack_bf2(l[2], l[3]);
        *(uint2*)(pAh + row * PITCH + c4 * 2) = hw;
        *(uint2*)(pAl + row * PITCH + c4 * 2) = lw;
    }
    __syncthreads();

    float acc[16][4];
    #pragma unroll
    for (int nt = 0; nt < 16; nt++)
        #pragma unroll
        for (int j = 0; j < 4; j++) acc[nt][j] = 0.0f;

    const int arow = warp * 16;

    // ---- pass 1: (Ah + Al) @ Bh ----
    #pragma unroll
    for (int k8 = 0; k8 < 8; k8++) {
        uint32_t abase = (uint32_t)(arow + g) * PITCH + (uint32_t)k8 * 32 + 4u * tig;
        uint32_t ah[4], al[4];
        ah[0] = *(const uint32_t*)(pAh + abase);
        ah[1] = *(const uint32_t*)(pAh + abase + 8 * PITCH);
        ah[2] = *(const uint32_t*)(pAh + abase + 16);
        ah[3] = *(const uint32_t*)(pAh + abase + 8 * PITCH + 16);
        al[0] = *(const uint32_t*)(pAl + abase);
        al[1] = *(const uint32_t*)(pAl + abase + 8 * PITCH);
        al[2] = *(const uint32_t*)(pAl + abase + 16);
        al[3] = *(const uint32_t*)(pAl + abase + 8 * PITCH + 16);
        #pragma unroll
        for (int nt = 0; nt < 16; nt++) {
            uint32_t boff = (uint32_t)(nt * 8 + g) * PITCH + 4u * tig + k8 * 32;
            uint32_t b0 = *(const uint32_t*)(pBh + boff);
            uint32_t b1 = *(const uint32_t*)(pBh + boff + 16);
            asm volatile(
                "mma.sync.aligned.m16n8k16.row.col.f32.bf16.bf16.f32 "
                "{%0,%1,%2,%3}, {%4,%5,%6,%7}, {%8,%9}, {%0,%1,%2,%3};"
                : "+f"(acc[nt][0]), "+f"(acc[nt][1]),
                  "+f"(acc[nt][2]), "+f"(acc[nt][3])
                : "r"(ah[0]), "r"(ah[1]), "r"(ah[2]), "r"(ah[3]),
                  "r"(b0), "r"(b1));
            asm volatile(
                "mma.sync.aligned.m16n8k16.row.col.f32.bf16.bf16.f32 "
                "{%0,%1,%2,%3}, {%4,%5,%6,%7}, {%8,%9}, {%0,%1,%2,%3};"
                : "+f"(acc[nt][0]), "+f"(acc[nt][1]),
                  "+f"(acc[nt][2]), "+f"(acc[nt][3])
                : "r"(al[0]), "r"(al[1]), "r"(al[2]), "r"(al[3]),
                  "r"(b0), "r"(b1));
        }
    }
    // ---- pass 2: Ah @ Bl ----
    #pragma unroll
    for (int k8 = 0; k8 < 8; k8++) {
        uint32_t abase = (uint32_t)(arow + g) * PITCH + (uint32_t)k8 * 32 + 4u * tig;
        uint32_t ah[4];
        ah[0] = *(const uint32_t*)(pAh + abase);
        ah[1] = *(const uint32_t*)(pAh + abase + 8 * PITCH);
        ah[2] = *(const uint32_t*)(pAh + abase + 16);
        ah[3] = *(const uint32_t*)(pAh + abase + 8 * PITCH + 16);
        #pragma unroll
        for (int nt = 0; nt < 16; nt++) {
            uint32_t boff = (uint32_t)(nt * 8 + g) * PITCH + 4u * tig + k8 * 32;
            uint32_t b0 = *(const uint32_t*)(pBl + boff);
            uint32_t b1 = *(const uint32_t*)(pBl + boff + 16);
            asm volatile(
                "mma.sync.aligned.m16n8k16.row.col.f32.bf16.bf16.f32 "
                "{%0,%1,%2,%3}, {%4,%5,%6,%7}, {%8,%9}, {%0,%1,%2,%3};"
                : "+f"(acc[nt][0]), "+f"(acc[nt][1]),
                  "+f"(acc[nt][2]), "+f"(acc[nt][3])
                : "r"(ah[0]), "r"(ah[1]), "r"(ah[2]), "r"(ah[3]),
                  "r"(b0), "r"(b1));
        }
    }

    const int r0 = m0 + arow + g;
    const int r1 = r0 + 8;
    #pragma unroll
    for (int nt = 0; nt < 16; nt++) {
        int col = nt * 8 + tig * 2;
        float bx = s_bias[col], by = s_bias[col + 1];
        if (r0 < M) {
            float2 o = make_float2(acc[nt][0] + bx, acc[nt][1] + by);
            *(float2*)(C + (size_t)r0 * 128 + col) = o;
        }
        if (r1 < M) {
            float2 o = make_float2(acc[nt][2] + bx, acc[nt][3] + by);
            *(float2*)(C + (size_t)r1 * 128 + col) = o;
        }
    }
}

// ------------------------------------------------------------------
// CSR aggregation + fused BN statistics.  One warp per destination
// node (lane owns 4 feats).  Branch-free masked 8-wide batches:
// every edge goes through one 24-load batch (8 epack + 8 enrm + 8 h),
// invalid slots clamp to end-1 with nrm forced to 0 -> no serial tail.
// ------------------------------------------------------------------
__global__ __launch_bounds__(256)
void k_aggr(const float* __restrict__ h, const float* __restrict__ We,
            const float* __restrict__ be, double* __restrict__ stats, int M)
{
    __shared__ double sm_s[128], sm_s2[128];
    const int tid  = threadIdx.x;
    const int lane = tid & 31;
    const int warp = (blockIdx.x * blockDim.x + tid) >> 5;
    const int nw   = (gridDim.x * blockDim.x) >> 5;
    const int f    = lane << 2;

    if (tid < 128) { sm_s[tid] = 0.0; sm_s2[tid] = 0.0; }
    __syncthreads();

    const float4 w0 = *(const float4*)(We + f);
    const float4 w1 = *(const float4*)(We + D + f);
    const float4 w2 = *(const float4*)(We + 2 * D + f);
    const float4 b4 = *(const float4*)(be + f);

    float ps[4]  = {0.f, 0.f, 0.f, 0.f};
    float ps2[4] = {0.f, 0.f, 0.f, 0.f};

    for (int n = warp; n < M; n += nw) {
        const int beg = g_colptr[n];
        const int end = g_colptr[n + 1];
        float4 acc = make_float4(0.f, 0.f, 0.f, 0.f);

        for (int pos = beg; pos < end; pos += 8) {
            int idx[8];
            #pragma unroll
            for (int u = 0; u < 8; u++) {
                int q = pos + u;
                idx[u] = (q < end) ? q : (end - 1);
            }
            int4   ee[8];
            float  nr[8];
            float4 hh[8];
            #pragma unroll
            for (int u = 0; u < 8; u++) ee[u] = g_epack[idx[u]];
            #pragma unroll
            for (int u = 0; u < 8; u++)
                nr[u] = (pos + u < end) ? g_enrm[idx[u]] : 0.0f;
            #pragma unroll
            for (int u = 0; u < 8; u++)
                hh[u] = *(const float4*)(h + (size_t)ee[u].x * D + f);
            #pragma unroll
            for (int u = 0; u < 8; u++) {
                float a0 = __int_as_float(ee[u].y);
                float a1 = __int_as_float(ee[u].z);
                float a2 = __int_as_float(ee[u].w);
                acc.x += fmaxf(hh[u].x + b4.x + a0*w0.x + a1*w1.x + a2*w2.x, 0.f) * nr[u];
                acc.y += fmaxf(hh[u].y + b4.y + a0*w0.y + a1*w1.y + a2*w2.y, 0.f) * nr[u];
                acc.z += fmaxf(hh[u].z + b4.z + a0*w0.z + a1*w1.z + a2*w2.z, 0.f) * nr[u];
                acc.w += fmaxf(hh[u].w + b4.w + a0*w0.w + a1*w1.w + a2*w2.w, 0.f) * nr[u];
            }
        }
        *(float4*)(g_acc + (size_t)n * D + f) = acc;

        // fused BN stats over relu(acc)
        float r0 = fmaxf(acc.x, 0.f), r1 = fmaxf(acc.y, 0.f);
        float r2 = fmaxf(acc.z, 0.f), r3 = fmaxf(acc.w, 0.f);
        ps[0] += r0; ps2[0] += r0 * r0;
        ps[1] += r1; ps2[1] += r1 * r1;
        ps[2] += r2; ps2[2] += r2 * r2;
        ps[3] += r3; ps2[3] += r3 * r3;
    }

    #pragma unroll
    for (int j = 0; j < 4; j++) {
        atomicAdd(&sm_s[f + j],  (double)ps[j]);
        atomicAdd(&sm_s2[f + j], (double)ps2[j]);
    }
    __syncthreads();
    if (tid < 128) {
        atomicAdd(&stats[tid],     sm_s[tid]);
        atomicAdd(&stats[D + tid], sm_s2[tid]);
    }
}

// ------------------------------------------------------------------
extern "C" void kernel_launch(void* const* d_in, const int* in_sizes, int n_in,
                              void* d_out, int out_size)
{
    const float* x  = (const float*)d_in[0];
    const int*   ei = (const int*)d_in[1];
    const float* ea = (const float*)d_in[2];
    const float* Wp[3]  = {(const float*)d_in[3],  (const float*)d_in[9],  (const float*)d_in[15]};
    const float* bp[3]  = {(const float*)d_in[4],  (const float*)d_in[10], (const float*)d_in[16]};
    const float* Wep[3] = {(const float*)d_in[5],  (const float*)d_in[11], (const float*)d_in[17]};
    const float* bep[3] = {(const float*)d_in[6],  (const float*)d_in[12], (const float*)d_in[18]};
    const float* gp[3]  = {(const float*)d_in[7],  (const float*)d_in[13], (const float*)d_in[19]};
    const float* btp[3] = {(const float*)d_in[8],  (const float*)d_in[14], (const float*)d_in[20]};
    const float* Wl = (const float*)d_in[21];
    const float* bl = (const float*)d_in[22];

    const int M = in_sizes[0] / D;
    const int E = in_sizes[1] / 2;

    // Resolve __device__ symbols via the runtime (GB300 ATS pitfall).
    void *p_h, *p_acc, *p_dinv, *p_stats, *p_wbh, *p_wbl, *p_colcnt;
    cudaGetSymbolAddress(&p_h, g_h);
    cudaGetSymbolAddress(&p_acc, g_acc);
    cudaGetSymbolAddress(&p_dinv, g_dinv);
    cudaGetSymbolAddress(&p_stats, g_stats4);
    cudaGetSymbolAddress(&p_wbh, g_wbh);
    cudaGetSymbolAddress(&p_wbl, g_wbl);
    cudaGetSymbolAddress(&p_colcnt, g_colcnt);
    const __nv_bfloat16* wbh = (const __nv_bfloat16*)p_wbh;
    const __nv_bfloat16* wbl = (const __nv_bfloat16*)p_wbl;
    double* stats = (double*)p_stats;   // [4][2*D]

    cudaFuncSetAttribute(k_gemm_mma, cudaFuncAttributeMaxDynamicSharedMemorySize,
                         DYNSMEM);

    // secondary stream + fork/join events (created once; graph-capturable)
    static cudaStream_t s2 = nullptr;
    static cudaEvent_t evA = nullptr, evB = nullptr;
    if (!s2) {
        cudaStreamCreate(&s2);
        cudaEventCreateWithFlags(&evA, cudaEventDisableTiming);
        cudaEventCreateWithFlags(&evB, cudaEventDisableTiming);
    }

    // ---- fork: CSR/degree build + stats zero on s2; wconv+gemm1 main ----
    cudaEventRecord(evA, 0);
    cudaStreamWaitEvent(s2, evA, 0);

    cudaMemsetAsync(p_stats, 0, 4 * 2 * D * sizeof(double), s2);
    cudaMemsetAsync(p_dinv, 0, (size_t)M * sizeof(float), s2);
    cudaMemsetAsync(p_colcnt, 0, (size_t)M * sizeof(int), s2);
    k_count<<<2048, 256, 0, s2>>>(ei, E);
    k_dinv<<<(M + 255) / 256, 256, 0, s2>>>(M);
    const int nb = (M + 1023) / 1024;
    k_scan1<<<nb, 1024, 0, s2>>>(M);
    k_scan2<<<1, 128, 0, s2>>>(nb);
    k_scan3<<<(M + 255) / 256, 256, 0, s2>>>(M, E);
    k_fill<<<2048, 256, 0, s2>>>(ei, ea, E);
    cudaEventRecord(evB, s2);

    const int gemm_grid = (M + 127) / 128;
    k_wconv<<<(4 * WTILE + 255) / 256, 256>>>(Wp[0], Wp[1], Wp[2], Wl);
    // layer-1 GEMM (no BN) overlaps the CSR build
    k_gemm_mma<<<gemm_grid, 256, DYNSMEM>>>(x, wbh, wbl, bp[0],
                                            nullptr, nullptr, nullptr,
                                            (float*)p_h, M);
    cudaStreamWaitEvent(0, evB, 0);   // join before first aggregation

    for (int L = 0; L < 3; L++) {
        if (L > 0)
            k_gemm_mma<<<gemm_grid, 256, DYNSMEM>>>((const float*)p_acc,
                                                    wbh + L * WTILE,
                                                    wbl + L * WTILE, bp[L],
                                                    gp[L - 1], btp[L - 1],
                                                    stats + (L - 1) * 2 * D,
                                                    (float*)p_h, M);
        k_aggr<<<2048, 256>>>((const float*)p_h, Wep[L], bep[L],
                              stats + L * 2 * D, M);
    }
    k_gemm_mma<<<gemm_grid, 256, DYNSMEM>>>((const float*)p_acc,
                                            wbh + 3 * WTILE, wbl + 3 * WTILE,
                                            bl, gp[2], btp[2],
                                            stats + 2 * 2 * D,
                                            (float*)d_out, M);
}